// round 5
// baseline (speedup 1.0000x reference)
#include <cuda_runtime.h>
#include <math.h>

#define S_ 1024
#define D_ 1024
#define H_ 16
#define EPSF 1e-5f
typedef unsigned long long ull;

__device__ float g_qt [2*H_*64*S_];   // [bh][d][s] transposed
__device__ float g_kt [2*H_*64*S_];
__device__ float g_vt [2*H_*S_*64];   // [bh][s][d]
__device__ float g_qns[2*H_*S_];
__device__ float g_kns[2*H_*S_];
__device__ float g_att[2*S_*D_];

__device__ __forceinline__ void fma2(ull&d,ull a,ull b){asm("fma.rn.f32x2 %0,%1,%2,%0;":"+l"(d):"l"(a),"l"(b));}
__device__ __forceinline__ void mul2(ull&d,ull a,ull b){asm("mul.rn.f32x2 %0,%1,%2;":"=l"(d):"l"(a),"l"(b));}
__device__ __forceinline__ float2 u2f(ull v){float2 r;asm("mov.b64 {%0,%1},%2;":"=f"(r.x),"=f"(r.y):"l"(v));return r;}
__device__ __forceinline__ ull f2u(float a,float b){ull r;asm("mov.b64 %0,{%1,%2};":"=l"(r):"f"(a),"f"(b));return r;}
__device__ __forceinline__ float sqap(float x){float r;asm("sqrt.approx.f32 %0,%1;":"=f"(r):"f"(x));return r;}
__device__ __forceinline__ float lg2ap(float x){float r;asm("lg2.approx.f32 %0,%1;":"=f"(r):"f"(x));return r;}
__device__ __forceinline__ float ex2ap(float x){float r;asm("ex2.approx.f32 %0,%1;":"=f"(r):"f"(x));return r;}
__device__ __forceinline__ float sp(float x){return log1pf(expf(x));}

// ===== GEMM: C = A @ W^T. EPI=0: qkv fused maps; EPI=1: plain out-proj =====
template<int EPI>
__global__ __launch_bounds__(256) void gemm_k(
    const float* __restrict__ A,const float* __restrict__ W0,
    const float* __restrict__ W1,const float* __restrict__ W2,
    const float* __restrict__ logc,float* __restrict__ Cout)
{
    __shared__ float As[16*132], Bsd[16*132];
    const int z=(EPI==0)?blockIdx.z:3;
    const float* __restrict__ W=(z==1)?W1:((z==2)?W2:W0);
    const float* __restrict__ Ain=(EPI==0)?A:(const float*)g_att;
    const int m0=blockIdx.y*128,n0=blockIdx.x*64,tid=threadIdx.x;
    const int tx=tid&15,ty=tid>>4;
    ull acc[4][4]={};
    const float4* A4=(const float4*)Ain; const float4* W4=(const float4*)W;
    const int ar=tid>>2,kq=tid&3;
    float4 pa0=A4[(size_t)(m0+ar)*256+kq];
    float4 pa1=A4[(size_t)(m0+ar+64)*256+kq];
    float4 pb =W4[(size_t)(n0+ar)*256+kq];
    for(int kt=0;kt<64;++kt){
        As[(kq*4+0)*132+ar]=pa0.x; As[(kq*4+1)*132+ar]=pa0.y;
        As[(kq*4+2)*132+ar]=pa0.z; As[(kq*4+3)*132+ar]=pa0.w;
        As[(kq*4+0)*132+ar+64]=pa1.x; As[(kq*4+1)*132+ar+64]=pa1.y;
        As[(kq*4+2)*132+ar+64]=pa1.z; As[(kq*4+3)*132+ar+64]=pa1.w;
        Bsd[(kq*4+0)*132+2*ar]=pb.x; Bsd[(kq*4+0)*132+2*ar+1]=pb.x;
        Bsd[(kq*4+1)*132+2*ar]=pb.y; Bsd[(kq*4+1)*132+2*ar+1]=pb.y;
        Bsd[(kq*4+2)*132+2*ar]=pb.z; Bsd[(kq*4+2)*132+2*ar+1]=pb.z;
        Bsd[(kq*4+3)*132+2*ar]=pb.w; Bsd[(kq*4+3)*132+2*ar+1]=pb.w;
        __syncthreads();
        if(kt<63){
            pa0=A4[(size_t)(m0+ar)*256+(kt+1)*4+kq];
            pa1=A4[(size_t)(m0+ar+64)*256+(kt+1)*4+kq];
            pb =W4[(size_t)(n0+ar)*256+(kt+1)*4+kq];
        }
        #pragma unroll
        for(int kk=0;kk<16;++kk){
            ulonglong2 a01=*(const ulonglong2*)&As[kk*132+ty*8];
            ulonglong2 a23=*(const ulonglong2*)&As[kk*132+ty*8+4];
            ulonglong2 b01=*(const ulonglong2*)&Bsd[kk*132+tx*8];
            ulonglong2 b23=*(const ulonglong2*)&Bsd[kk*132+tx*8+4];
            fma2(acc[0][0],a01.x,b01.x); fma2(acc[0][1],a01.x,b01.y);
            fma2(acc[0][2],a01.x,b23.x); fma2(acc[0][3],a01.x,b23.y);
            fma2(acc[1][0],a01.y,b01.x); fma2(acc[1][1],a01.y,b01.y);
            fma2(acc[1][2],a01.y,b23.x); fma2(acc[1][3],a01.y,b23.y);
            fma2(acc[2][0],a23.x,b01.x); fma2(acc[2][1],a23.x,b01.y);
            fma2(acc[2][2],a23.x,b23.x); fma2(acc[2][3],a23.x,b23.y);
            fma2(acc[3][0],a23.y,b01.x); fma2(acc[3][1],a23.y,b01.y);
            fma2(acc[3][2],a23.y,b23.x); fma2(acc[3][3],a23.y,b23.y);
        }
        __syncthreads();
    }
    if(EPI==1){
        #pragma unroll
        for(int ip=0;ip<4;++ip){
            float2 f0=u2f(acc[ip][0]),f1=u2f(acc[ip][1]),f2=u2f(acc[ip][2]),f3=u2f(acc[ip][3]);
            int m=m0+ty*8+2*ip;
            *(float4*)&Cout[(size_t)m*D_+n0+tx*4]    =make_float4(f0.x,f1.x,f2.x,f3.x);
            *(float4*)&Cout[(size_t)(m+1)*D_+n0+tx*4]=make_float4(f0.y,f1.y,f2.y,f3.y);
        }
        return;
    }
    const float c_=sp(*logc), sc=sqrtf(c_);
    const int hh=blockIdx.x;
    #pragma unroll
    for(int ip=0;ip<4;++ip){
        float2 f[4];
        #pragma unroll
        for(int j=0;j<4;++j) f[j]=u2f(acc[ip][j]);
        #pragma unroll
        for(int h2=0;h2<2;++h2){
            int m=m0+ty*8+2*ip+h2, b=m>>10, s=m&1023, bh=b*H_+hh;
            float e0=h2?f[0].y:f[0].x, e1=h2?f[1].y:f[1].x;
            float e2=h2?f[2].y:f[2].x, e3=h2?f[3].y:f[3].x;
            float ss=e0*e0+e1*e1+e2*e2+e3*e3;
            ss+=__shfl_xor_sync(~0u,ss,1); ss+=__shfl_xor_sync(~0u,ss,2);
            ss+=__shfl_xor_sync(~0u,ss,4); ss+=__shfl_xor_sync(~0u,ss,8);
            float n=fmaxf(sqrtf(ss),EPSF), scn=sc*n, t1=tanhf(scn);
            float scale;
            if(z<2) scale=t1/scn;
            else { float th=1.f-sc*EPSF; scale=(t1<th)?1.f:(atanhf(th)/scn); }
            e0*=scale; e1*=scale; e2*=scale; e3*=scale;
            if(z==2){
                *(float4*)&g_vt[((size_t)bh*S_+s)*64+tx*4]=make_float4(e0,e1,e2,e3);
            }else{
                float* __restrict__ T=(z==0)?g_qt:g_kt;
                size_t base=(size_t)bh*64*S_+s;
                T[base+(size_t)(tx*4+0)*S_]=e0; T[base+(size_t)(tx*4+1)*S_]=e1;
                T[base+(size_t)(tx*4+2)*S_]=e2; T[base+(size_t)(tx*4+3)*S_]=e3;
                if(tx==0) ((z==0)?g_qns:g_kns)[bh*S_+s]=scale*scale*ss;
            }
        }
    }
}

// ===== Attention: 64q x 64k tiles, log2-space scores, packed FMA2 =====
#define QS 0
#define KS 4352
#define VS 12800
#define PS 21248
#define QN 25600
#define IOX 25664
#define KN 25728
#define IOY 25792
#define MR 25856
#define LR 25920
#define CR 25984
#define RED 26048
#define ASMF 26304
#define ASMB (ASMF*4)

__global__ __launch_bounds__(256) void attn_k(const float* __restrict__ lp,
                                              const float* __restrict__ bp)
{
    extern __shared__ float sm[];
    const int bh=blockIdx.y, q0=blockIdx.x*64, tid=threadIdx.x;
    const int tx=tid&15, ty=tid>>4;
    const float c_=sp(*lp), sc=sqrtf(c_), bis=sp(*bp)/sc, tc=2.f*c_;
    const float* __restrict__ Qt=g_qt+(size_t)bh*64*S_;
    const float* __restrict__ Kt=g_kt+(size_t)bh*64*S_;
    const float* __restrict__ Vg=g_vt+(size_t)bh*S_*64;

    #pragma unroll
    for(int u=0;u<4;++u){ int idx=tid+u*256, d=idx>>4, rq=idx&15;
        float4 v=*(const float4*)&Qt[(size_t)d*S_+q0+rq*4];
        *(float4*)&sm[QS+d*68+rq*4]=v; }
    if(tid<64){ float qn=g_qns[bh*S_+q0+tid]; sm[QN+tid]=qn;
        sm[IOX+tid]=__fdividef(1.f,1.f-c_*qn); sm[MR+tid]=-INFINITY; sm[LR+tid]=0.f; }

    ull o2[2][4]={};
    const int rr=tid&63, part=tid>>6;

    for(int kt=0;kt<16;++kt){
        const int k0=kt*64;
        __syncthreads();
        #pragma unroll
        for(int u=0;u<4;++u){ int idx=tid+u*256, d=idx>>4, tq=idx&15;
            float4 kv=*(const float4*)&Kt[(size_t)d*S_+k0+tq*4];
            float* kp=&sm[KS+d*132+8*tq];
            kp[0]=kv.x;kp[1]=kv.x;kp[2]=kv.y;kp[3]=kv.y;kp[4]=kv.z;kp[5]=kv.z;kp[6]=kv.w;kp[7]=kv.w;
            float4 vv=*(const float4*)&Vg[(size_t)(k0+d)*64+tq*4];
            float* vp=&sm[VS+d*132+8*tq];
            vp[0]=vv.x;vp[1]=vv.x;vp[2]=vv.y;vp[3]=vv.y;vp[4]=vv.z;vp[5]=vv.z;vp[6]=vv.w;vp[7]=vv.w;
        }
        if(tid<64){ float kn=g_kns[bh*S_+k0+tid]; sm[KN+tid]=kn;
            sm[IOY+tid]=__fdividef(1.f,1.f-c_*kn); }
        __syncthreads();

        ull s2[2][4]={};
        #pragma unroll 16
        for(int d=0;d<64;++d){
            ulonglong2 q01=*(const ulonglong2*)&sm[QS+d*68+ty*4];
            ulonglong2 k01=*(const ulonglong2*)&sm[KS+d*132+tx*8];
            ulonglong2 k23=*(const ulonglong2*)&sm[KS+d*132+tx*8+4];
            fma2(s2[0][0],q01.x,k01.x); fma2(s2[0][1],q01.x,k01.y);
            fma2(s2[0][2],q01.x,k23.x); fma2(s2[0][3],q01.x,k23.y);
            fma2(s2[1][0],q01.y,k01.x); fma2(s2[1][1],q01.y,k01.y);
            fma2(s2[1][2],q01.y,k23.x); fma2(s2[1][3],q01.y,k23.y);
        }
        {
            float qnr[4],ioxr[4];
            #pragma unroll
            for(int i=0;i<4;++i){ qnr[i]=sm[QN+ty*4+i]; ioxr[i]=sm[IOX+ty*4+i]; }
            #pragma unroll
            for(int j=0;j<4;++j){
                int t=tx*4+j;
                float2 sj0=u2f(s2[0][j]), sj1=u2f(s2[1][j]);
                float sv[4]={sj0.x,sj0.y,sj1.x,sj1.y};
                float knj=sm[KN+t], ioyj=sm[IOY+t], res[4];
                #pragma unroll
                for(int i=0;i<4;++i){
                    float dsq=fmaf(-2.f,sv[i],qnr[i]+knj);
                    float tt=fminf(ioxr[i]*ioyj,1.0e5f);
                    float arg=fmaxf(fmaf(tc*dsq,tt,1.f),1.f+EPSF);
                    float w=arg+sqap(fmaf(arg,arg,-1.f));
                    res[i]=-bis*lg2ap(w);
                }
                *(float4*)&sm[PS+t*68+ty*4]=make_float4(res[0],res[1],res[2],res[3]);
            }
        }
        __syncthreads();
        {
            float lmax=-INFINITY;
            #pragma unroll
            for(int k=0;k<16;++k) lmax=fmaxf(lmax,sm[PS+(part*16+k)*68+rr]);
            sm[RED+part*64+rr]=lmax;
        }
        __syncthreads();
        if(tid<64){
            float tm=fmaxf(fmaxf(sm[RED+tid],sm[RED+64+tid]),fmaxf(sm[RED+128+tid],sm[RED+192+tid]));
            float mo=sm[MR+tid], mn=fmaxf(mo,tm);
            sm[MR+tid]=mn; sm[CR+tid]=ex2ap(mo-mn);
        }
        __syncthreads();
        {
            float mv=sm[MR+rr], ls=0.f;
            #pragma unroll
            for(int k=0;k<16;++k){ int a=PS+(part*16+k)*68+rr;
                float p=ex2ap(sm[a]-mv); sm[a]=p; ls+=p; }
            sm[RED+part*64+rr]=ls;
        }
        #pragma unroll
        for(int i=0;i<2;++i){
            ull crd=f2u(sm[CR+ty*4+2*i],sm[CR+ty*4+2*i+1]);
            mul2(o2[i][0],o2[i][0],crd); mul2(o2[i][1],o2[i][1],crd);
            mul2(o2[i][2],o2[i][2],crd); mul2(o2[i][3],o2[i][3],crd);
        }
        __syncthreads();
        if(tid<64) sm[LR+tid]=sm[LR+tid]*sm[CR+tid]
            +sm[RED+tid]+sm[RED+64+tid]+sm[RED+128+tid]+sm[RED+192+tid];
        #pragma unroll 8
        for(int t=0;t<64;++t){
            ulonglong2 p01=*(const ulonglong2*)&sm[PS+t*68+ty*4];
            ulonglong2 v01=*(const ulonglong2*)&sm[VS+t*132+tx*8];
            ulonglong2 v23=*(const ulonglong2*)&sm[VS+t*132+tx*8+4];
            fma2(o2[0][0],p01.x,v01.x); fma2(o2[0][1],p01.x,v01.y);
            fma2(o2[0][2],p01.x,v23.x); fma2(o2[0][3],p01.x,v23.y);
            fma2(o2[1][0],p01.y,v01.x); fma2(o2[1][1],p01.y,v01.y);
            fma2(o2[1][2],p01.y,v23.x); fma2(o2[1][3],p01.y,v23.y);
        }
    }
    __syncthreads();
    const int b=bh>>4, hh=bh&15;
    #pragma unroll
    for(int i=0;i<2;++i){
        #pragma unroll
        for(int h2=0;h2<2;++h2){
            int r=ty*4+2*i+h2;
            float invl=__fdividef(1.f,sm[LR+r]);
            float e[4];
            #pragma unroll
            for(int j=0;j<4;++j){ float2 f=u2f(o2[i][j]); e[j]=(h2?f.y:f.x)*invl; }
            float ss=e[0]*e[0]+e[1]*e[1]+e[2]*e[2]+e[3]*e[3];
            ss+=__shfl_xor_sync(~0u,ss,1); ss+=__shfl_xor_sync(~0u,ss,2);
            ss+=__shfl_xor_sync(~0u,ss,4); ss+=__shfl_xor_sync(~0u,ss,8);
            float n=fmaxf(sqrtf(ss),EPSF), scn=sc*n, t1=tanhf(scn);
            float th=1.f-sc*EPSF;
            float scale=(t1<th)?1.f:(atanhf(th)/scn);
            *(float4*)&g_att[(size_t)(b*S_+q0+r)*D_+hh*64+tx*4]
                =make_float4(e[0]*scale,e[1]*scale,e[2]*scale,e[3]*scale);
        }
    }
}

extern "C" void kernel_launch(void* const* d_in, const int* in_sizes, int n_in,
                              void* d_out, int out_size)
{
    (void)in_sizes;(void)n_in;(void)out_size;
    const float* x   =(const float*)d_in[0];
    const float* Wq  =(const float*)d_in[1];
    const float* Wk  =(const float*)d_in[2];
    const float* Wv  =(const float*)d_in[3];
    const float* Wo  =(const float*)d_in[4];
    const float* logc=(const float*)d_in[5];
    const float* beta=(const float*)d_in[6];
    float* out=(float*)d_out;

    cudaFuncSetAttribute(attn_k, cudaFuncAttributeMaxDynamicSharedMemorySize, ASMB);

    gemm_k<0><<<dim3(16,16,3),256>>>(x,Wq,Wk,Wv,logc,nullptr);
    attn_k<<<dim3(16,32),256,ASMB>>>(logc,beta);
    gemm_k<1><<<dim3(16,16),256>>>(x,Wo,Wo,Wo,logc,out);
}

// round 7
// speedup vs baseline: 1.8577x; 1.8577x over previous
#include <cuda_runtime.h>
#include <math.h>

#define S_ 1024
#define D_ 1024
#define H_ 16
#define EPSF 1e-5f
typedef unsigned long long ull;

__device__ float g_qt [2*H_*64*S_];   // [bh][d][s]
__device__ float g_kt [2*H_*64*S_];
__device__ float g_vt [2*H_*S_*64];   // [bh][s][d]
__device__ float g_qns[2*H_*S_];
__device__ float g_kns[2*H_*S_];
__device__ float g_att[2*S_*D_];

__device__ __forceinline__ void fma2(ull&d,ull a,ull b){asm("fma.rn.f32x2 %0,%1,%2,%0;":"+l"(d):"l"(a),"l"(b));}
__device__ __forceinline__ void mul2(ull&d,ull a,ull b){asm("mul.rn.f32x2 %0,%1,%2;":"=l"(d):"l"(a),"l"(b));}
__device__ __forceinline__ float2 u2f(ull v){float2 r;asm("mov.b64 {%0,%1},%2;":"=f"(r.x),"=f"(r.y):"l"(v));return r;}
__device__ __forceinline__ ull f2u(float a,float b){ull r;asm("mov.b64 %0,{%1,%2};":"=l"(r):"f"(a),"f"(b));return r;}
__device__ __forceinline__ float sqap(float x){float r;asm("sqrt.approx.f32 %0,%1;":"=f"(r):"f"(x));return r;}
__device__ __forceinline__ float lg2ap(float x){float r;asm("lg2.approx.f32 %0,%1;":"=f"(r):"f"(x));return r;}
__device__ __forceinline__ float ex2ap(float x){float r;asm("ex2.approx.f32 %0,%1;":"=f"(r):"f"(x));return r;}
__device__ __forceinline__ float sp(float x){return log1pf(expf(x));}

// ===== GEMM: C = A @ W^T. BM=128,BN=128,BK=16. A dup in smem, B natural =====
template<int EPI>
__global__ __launch_bounds__(256,2) void gemm_k(
    const float* __restrict__ A,const float* __restrict__ W0,
    const float* __restrict__ W1,const float* __restrict__ W2,
    const float* __restrict__ logc,float* __restrict__ Cout)
{
    __shared__ float Asd[16*268];   // [k][2m dup]
    __shared__ float Bs [16*132];   // [k][n]
    const int z=(EPI==0)?blockIdx.z:3;
    const float* __restrict__ W=(z==1)?W1:((z==2)?W2:W0);
    const float* __restrict__ Ain=(EPI==0)?A:(const float*)g_att;
    const int m0=blockIdx.y*128,n0=blockIdx.x*128,tid=threadIdx.x;
    const int tx=tid&15,ty=tid>>4;
    ull acc[8][4]={};
    const float4* A4=(const float4*)Ain; const float4* W4=(const float4*)W;
    const int ar=tid>>2,kq=tid&3;
    float4 pa0=A4[(size_t)(m0+ar)*256+kq];
    float4 pa1=A4[(size_t)(m0+ar+64)*256+kq];
    float4 pb0=W4[(size_t)(n0+ar)*256+kq];
    float4 pb1=W4[(size_t)(n0+ar+64)*256+kq];
    for(int kt=0;kt<64;++kt){
        {
            float av0[4]={pa0.x,pa0.y,pa0.z,pa0.w};
            float av1[4]={pa1.x,pa1.y,pa1.z,pa1.w};
            float bv0[4]={pb0.x,pb0.y,pb0.z,pb0.w};
            float bv1[4]={pb1.x,pb1.y,pb1.z,pb1.w};
            #pragma unroll
            for(int c=0;c<4;++c){
                int krow=kq*4+c;
                *(ull*)&Asd[krow*268+2*ar]      =f2u(av0[c],av0[c]);
                *(ull*)&Asd[krow*268+2*ar+128]  =f2u(av1[c],av1[c]);
                Bs[krow*132+ar]   =bv0[c];
                Bs[krow*132+ar+64]=bv1[c];
            }
        }
        __syncthreads();
        if(kt<63){
            pa0=A4[(size_t)(m0+ar)*256+(kt+1)*4+kq];
            pa1=A4[(size_t)(m0+ar+64)*256+(kt+1)*4+kq];
            pb0=W4[(size_t)(n0+ar)*256+(kt+1)*4+kq];
            pb1=W4[(size_t)(n0+ar+64)*256+(kt+1)*4+kq];
        }
        #pragma unroll
        for(int kk=0;kk<16;++kk){
            ulonglong2 a0=*(const ulonglong2*)&Asd[kk*268+16*ty];
            ulonglong2 a1=*(const ulonglong2*)&Asd[kk*268+16*ty+4];
            ulonglong2 a2=*(const ulonglong2*)&Asd[kk*268+16*ty+8];
            ulonglong2 a3=*(const ulonglong2*)&Asd[kk*268+16*ty+12];
            ulonglong2 b0=*(const ulonglong2*)&Bs[kk*132+tx*4];
            ulonglong2 b1=*(const ulonglong2*)&Bs[kk*132+64+tx*4];
            ull ad[8]={a0.x,a0.y,a1.x,a1.y,a2.x,a2.y,a3.x,a3.y};
            #pragma unroll
            for(int i=0;i<8;++i){
                fma2(acc[i][0],ad[i],b0.x); fma2(acc[i][1],ad[i],b0.y);
                fma2(acc[i][2],ad[i],b1.x); fma2(acc[i][3],ad[i],b1.y);
            }
        }
        __syncthreads();
    }
    if(EPI==1){
        #pragma unroll
        for(int i=0;i<8;++i){
            int m=m0+ty*8+i;
            float2 c0=u2f(acc[i][0]),c1=u2f(acc[i][1]),c2=u2f(acc[i][2]),c3=u2f(acc[i][3]);
            *(float4*)&Cout[(size_t)m*D_+n0+tx*4]   =make_float4(c0.x,c0.y,c1.x,c1.y);
            *(float4*)&Cout[(size_t)m*D_+n0+64+tx*4]=make_float4(c2.x,c2.y,c3.x,c3.y);
        }
        return;
    }
    const float c_=sp(*logc), sc=sqrtf(c_);
    #pragma unroll
    for(int i=0;i<8;++i){
        int m=m0+ty*8+i, b=m>>10, s=m&1023;
        #pragma unroll
        for(int j=0;j<2;++j){
            int hh=blockIdx.x*2+j, bh=b*H_+hh;
            float2 f0=u2f(acc[i][2*j]), f1=u2f(acc[i][2*j+1]);
            float e0=f0.x,e1=f0.y,e2=f1.x,e3=f1.y;
            float ss=e0*e0+e1*e1+e2*e2+e3*e3;
            ss+=__shfl_xor_sync(~0u,ss,1); ss+=__shfl_xor_sync(~0u,ss,2);
            ss+=__shfl_xor_sync(~0u,ss,4); ss+=__shfl_xor_sync(~0u,ss,8);
            float n=fmaxf(sqrtf(ss),EPSF), scn=sc*n, t1=tanhf(scn);
            float scale;
            if(z<2) scale=t1/scn;
            else { float th=1.f-sc*EPSF; scale=(t1<th)?1.f:(atanhf(th)/scn); }
            e0*=scale;e1*=scale;e2*=scale;e3*=scale;
            if(z==2){
                *(float4*)&g_vt[((size_t)bh*S_+s)*64+tx*4]=make_float4(e0,e1,e2,e3);
            }else{
                float* __restrict__ T=(z==0)?g_qt:g_kt;
                size_t base=(size_t)bh*64*S_+s;
                T[base+(size_t)(tx*4+0)*S_]=e0; T[base+(size_t)(tx*4+1)*S_]=e1;
                T[base+(size_t)(tx*4+2)*S_]=e2; T[base+(size_t)(tx*4+3)*S_]=e3;
                if(tx==0) ((z==0)?g_qns:g_kns)[bh*S_+s]=scale*scale*ss;
            }
        }
    }
}

// ===== Attention: 128q x 64k tiles. Q natural pairs, K/V dup, P pairs =====
#define QS0 0
#define KSD 8448
#define VSD 16896
#define PSS 25344
#define KNO 33792
#define IOYO 33856
#define ASMF 33920
#define ASMB (ASMF*4)

__global__ __launch_bounds__(256) void attn_k(const float* __restrict__ lp,
                                              const float* __restrict__ bp)
{
    extern __shared__ float sm[];
    const int bh=blockIdx.y, q0=blockIdx.x*128, tid=threadIdx.x;
    const int tx=tid&15, ty=tid>>4;
    const float c_=sp(*lp), sc=sqrtf(c_), bis=sp(*bp)/sc, tc=2.f*c_;
    const float* __restrict__ Qt=g_qt+(size_t)bh*64*S_;
    const float* __restrict__ Kt=g_kt+(size_t)bh*64*S_;
    const float* __restrict__ Vg=g_vt+(size_t)bh*S_*64;

    #pragma unroll
    for(int u=0;u<8;++u){ int idx=tid+u*256, d=idx>>5, qq=idx&31;
        *(float4*)&sm[QS0+d*132+qq*4]=*(const float4*)&Qt[(size_t)d*S_+q0+qq*4]; }

    ull qn2[4], iox2[4];
    #pragma unroll
    for(int i=0;i<4;++i){
        float a=g_qns[bh*S_+q0+ty*8+2*i], b=g_qns[bh*S_+q0+ty*8+2*i+1];
        qn2[i]=f2u(a,b);
        iox2[i]=f2u(__fdividef(1.f,1.f-c_*a),__fdividef(1.f,1.f-c_*b));
    }
    float mrow[8], lrow[8];
    #pragma unroll
    for(int r=0;r<8;++r){ mrow[r]=-INFINITY; lrow[r]=0.f; }
    ull o[4][4]={};
    const int kc0=2*tx, kc2=2*tx+32;

    for(int kt=0;kt<16;++kt){
        const int k0=kt*64;
        __syncthreads();
        #pragma unroll
        for(int u=0;u<4;++u){ int idx=tid+u*256, d=idx>>4, kq=idx&15;
            float4 kv=*(const float4*)&Kt[(size_t)d*S_+k0+kq*4];
            ull* kp=(ull*)&sm[KSD+d*132+kq*8];
            kp[0]=f2u(kv.x,kv.x); kp[1]=f2u(kv.y,kv.y);
            kp[2]=f2u(kv.z,kv.z); kp[3]=f2u(kv.w,kv.w);
            float4 vv=*(const float4*)&Vg[(size_t)(k0+d)*64+kq*4];
            ull* vp=(ull*)&sm[VSD+d*132+kq*8];
            vp[0]=f2u(vv.x,vv.x); vp[1]=f2u(vv.y,vv.y);
            vp[2]=f2u(vv.z,vv.z); vp[3]=f2u(vv.w,vv.w);
        }
        if(tid<64){ float kn=g_kns[bh*S_+k0+tid];
            sm[KNO+tid]=kn; sm[IOYO+tid]=__fdividef(1.f,1.f-c_*kn); }
        __syncthreads();

        // S = Q K^T : s2[i][c] = (q_{2i}.k_c, q_{2i+1}.k_c)
        ull s2[4][4]={};
        #pragma unroll 16
        for(int d=0;d<64;++d){
            ulonglong2 qa=*(const ulonglong2*)&sm[QS0+d*132+ty*8];
            ulonglong2 qb=*(const ulonglong2*)&sm[QS0+d*132+ty*8+4];
            ulonglong2 ka=*(const ulonglong2*)&sm[KSD+d*132+tx*4];
            ulonglong2 kb=*(const ulonglong2*)&sm[KSD+d*132+64+tx*4];
            fma2(s2[0][0],qa.x,ka.x); fma2(s2[0][1],qa.x,ka.y);
            fma2(s2[0][2],qa.x,kb.x); fma2(s2[0][3],qa.x,kb.y);
            fma2(s2[1][0],qa.y,ka.x); fma2(s2[1][1],qa.y,ka.y);
            fma2(s2[1][2],qa.y,kb.x); fma2(s2[1][3],qa.y,kb.y);
            fma2(s2[2][0],qb.x,ka.x); fma2(s2[2][1],qb.x,ka.y);
            fma2(s2[2][2],qb.x,kb.x); fma2(s2[2][3],qb.x,kb.y);
            fma2(s2[3][0],qb.y,ka.x); fma2(s2[3][1],qb.y,ka.y);
            fma2(s2[3][2],qb.y,kb.x); fma2(s2[3][3],qb.y,kb.y);
        }
        // scores
        float kns[4],ioys[4];
        kns[0]=sm[KNO+kc0]; kns[1]=sm[KNO+kc0+1]; kns[2]=sm[KNO+kc2]; kns[3]=sm[KNO+kc2+1];
        ioys[0]=sm[IOYO+kc0]; ioys[1]=sm[IOYO+kc0+1]; ioys[2]=sm[IOYO+kc2]; ioys[3]=sm[IOYO+kc2+1];
        float res[8][4];
        #pragma unroll
        for(int i=0;i<4;++i){
            float2 qn=u2f(qn2[i]), iox=u2f(iox2[i]);
            #pragma unroll
            for(int c=0;c<4;++c){
                float2 dot=u2f(s2[i][c]);
                float dsq0=fmaf(-2.f,dot.x,qn.x+kns[c]);
                float tt0=fminf(iox.x*ioys[c],1.0e5f);
                float a0=fmaxf(fmaf(tc*dsq0,tt0,1.f),1.f+EPSF);
                res[2*i][c]=-bis*lg2ap(a0+sqap(fmaf(a0,a0,-1.f)));
                float dsq1=fmaf(-2.f,dot.y,qn.y+kns[c]);
                float tt1=fminf(iox.y*ioys[c],1.0e5f);
                float a1=fmaxf(fmaf(tc*dsq1,tt1,1.f),1.f+EPSF);
                res[2*i+1][c]=-bis*lg2ap(a1+sqap(fmaf(a1,a1,-1.f)));
            }
        }
        // online softmax (stats in regs, shfl over tx = lane bits 0-3)
        float pcorr[8];
        #pragma unroll
        for(int r=0;r<8;++r){
            float tm=fmaxf(fmaxf(res[r][0],res[r][1]),fmaxf(res[r][2],res[r][3]));
            tm=fmaxf(tm,__shfl_xor_sync(~0u,tm,1));
            tm=fmaxf(tm,__shfl_xor_sync(~0u,tm,2));
            tm=fmaxf(tm,__shfl_xor_sync(~0u,tm,4));
            tm=fmaxf(tm,__shfl_xor_sync(~0u,tm,8));
            float mn=fmaxf(mrow[r],tm);
            pcorr[r]=ex2ap(mrow[r]-mn); mrow[r]=mn;
            float ls=0.f;
            #pragma unroll
            for(int c=0;c<4;++c){ float p=ex2ap(res[r][c]-mn); res[r][c]=p; ls+=p; }
            ls+=__shfl_xor_sync(~0u,ls,1); ls+=__shfl_xor_sync(~0u,ls,2);
            ls+=__shfl_xor_sync(~0u,ls,4); ls+=__shfl_xor_sync(~0u,ls,8);
            lrow[r]=lrow[r]*pcorr[r]+ls;
        }
        #pragma unroll
        for(int i=0;i<4;++i){
            ull cr=f2u(pcorr[2*i],pcorr[2*i+1]);
            mul2(o[i][0],o[i][0],cr); mul2(o[i][1],o[i][1],cr);
            mul2(o[i][2],o[i][2],cr); mul2(o[i][3],o[i][3],cr);
        }
        // store P pairs [k][q]
        #pragma unroll
        for(int i=0;i<4;++i){
            *(ull*)&sm[PSS+kc0*132    +ty*8+2*i]=f2u(res[2*i][0],res[2*i+1][0]);
            *(ull*)&sm[PSS+(kc0+1)*132+ty*8+2*i]=f2u(res[2*i][1],res[2*i+1][1]);
            *(ull*)&sm[PSS+kc2*132    +ty*8+2*i]=f2u(res[2*i][2],res[2*i+1][2]);
            *(ull*)&sm[PSS+(kc2+1)*132+ty*8+2*i]=f2u(res[2*i][3],res[2*i+1][3]);
        }
        __syncthreads();
        // O += P V
        #pragma unroll 16
        for(int kk=0;kk<64;++kk){
            ulonglong2 pa=*(const ulonglong2*)&sm[PSS+kk*132+ty*8];
            ulonglong2 pb=*(const ulonglong2*)&sm[PSS+kk*132+ty*8+4];
            ulonglong2 va=*(const ulonglong2*)&sm[VSD+kk*132+tx*4];
            ulonglong2 vb=*(const ulonglong2*)&sm[VSD+kk*132+64+tx*4];
            fma2(o[0][0],pa.x,va.x); fma2(o[0][1],pa.x,va.y);
            fma2(o[0][2],pa.x,vb.x); fma2(o[0][3],pa.x,vb.y);
            fma2(o[1][0],pa.y,va.x); fma2(o[1][1],pa.y,va.y);
            fma2(o[1][2],pa.y,vb.x); fma2(o[1][3],pa.y,vb.y);
            fma2(o[2][0],pb.x,va.x); fma2(o[2][1],pb.x,va.y);
            fma2(o[2][2],pb.x,vb.x); fma2(o[2][3],pb.x,vb.y);
            fma2(o[3][0],pb.y,va.x); fma2(o[3][1],pb.y,va.y);
            fma2(o[3][2],pb.y,vb.x); fma2(o[3][3],pb.y,vb.y);
        }
    }
    // finalize
    const int b=bh>>4, hh=bh&15;
    #pragma unroll
    for(int i=0;i<4;++i){
        #pragma unroll
        for(int h=0;h<2;++h){
            int r=ty*8+2*i+h;
            float invl=__fdividef(1.f,lrow[2*i+h]);
            float2 f0=u2f(o[i][0]),f1=u2f(o[i][1]),f2=u2f(o[i][2]),f3=u2f(o[i][3]);
            float e0=(h?f0.y:f0.x)*invl, e1=(h?f1.y:f1.x)*invl;
            float e2=(h?f2.y:f2.x)*invl, e3=(h?f3.y:f3.x)*invl;
            float ss=e0*e0+e1*e1+e2*e2+e3*e3;
            ss+=__shfl_xor_sync(~0u,ss,1); ss+=__shfl_xor_sync(~0u,ss,2);
            ss+=__shfl_xor_sync(~0u,ss,4); ss+=__shfl_xor_sync(~0u,ss,8);
            float n=fmaxf(sqrtf(ss),EPSF), scn=sc*n, t1=tanhf(scn);
            float th=1.f-sc*EPSF;
            float scale=(t1<th)?1.f:(atanhf(th)/scn);
            size_t dst=(size_t)(b*S_+q0+r)*D_+hh*64;
            *(float2*)&g_att[dst+2*tx]   =make_float2(e0*scale,e1*scale);
            *(float2*)&g_att[dst+32+2*tx]=make_float2(e2*scale,e3*scale);
        }
    }
}

extern "C" void kernel_launch(void* const* d_in, const int* in_sizes, int n_in,
                              void* d_out, int out_size)
{
    (void)in_sizes;(void)n_in;(void)out_size;
    const float* x   =(const float*)d_in[0];
    const float* Wq  =(const float*)d_in[1];
    const float* Wk  =(const float*)d_in[2];
    const float* Wv  =(const float*)d_in[3];
    const float* Wo  =(const float*)d_in[4];
    const float* logc=(const float*)d_in[5];
    const float* beta=(const float*)d_in[6];
    float* out=(float*)d_out;

    cudaFuncSetAttribute(attn_k, cudaFuncAttributeMaxDynamicSharedMemorySize, ASMB);

    gemm_k<0><<<dim3(8,16,3),256>>>(x,Wq,Wk,Wv,logc,nullptr);
    attn_k<<<dim3(8,32),256,ASMB>>>(logc,beta);
    gemm_k<1><<<dim3(8,16),256>>>(x,Wo,Wo,Wo,logc,out);
}

// round 10
// speedup vs baseline: 2.5485x; 1.3718x over previous
#include <cuda_runtime.h>
#include <cuda_bf16.h>
#include <math.h>
#include <stdint.h>

#define S_ 1024
#define D_ 1024
#define H_ 16
#define EPSF 1e-5f
typedef unsigned long long ull;

__device__ float g_qt [2*H_*64*S_];   // [bh][d][s]
__device__ float g_kt [2*H_*64*S_];
__device__ float g_vt [2*H_*S_*64];   // [bh][s][d]
__device__ float g_qns[2*H_*S_];
__device__ float g_kns[2*H_*S_];
__device__ float g_att[2*S_*D_];
__device__ __align__(16) __nv_bfloat16 g_xh[2048*1024];
__device__ __align__(16) __nv_bfloat16 g_xl[2048*1024];
__device__ __align__(16) __nv_bfloat16 g_wh[3*1024*1024];
__device__ __align__(16) __nv_bfloat16 g_wl[3*1024*1024];

__device__ __forceinline__ void fma2(ull&d,ull a,ull b){asm("fma.rn.f32x2 %0,%1,%2,%0;":"+l"(d):"l"(a),"l"(b));}
__device__ __forceinline__ void mul2(ull&d,ull a,ull b){asm("mul.rn.f32x2 %0,%1,%2;":"=l"(d):"l"(a),"l"(b));}
__device__ __forceinline__ float2 u2f(ull v){float2 r;asm("mov.b64 {%0,%1},%2;":"=f"(r.x),"=f"(r.y):"l"(v));return r;}
__device__ __forceinline__ ull f2u(float a,float b){ull r;asm("mov.b64 %0,{%1,%2};":"=l"(r):"f"(a),"f"(b));return r;}
__device__ __forceinline__ float sqap(float x){float r;asm("sqrt.approx.f32 %0,%1;":"=f"(r):"f"(x));return r;}
__device__ __forceinline__ float lg2ap(float x){float r;asm("lg2.approx.f32 %0,%1;":"=f"(r):"f"(x));return r;}
__device__ __forceinline__ float ex2ap(float x){float r;asm("ex2.approx.f32 %0,%1;":"=f"(r):"f"(x));return r;}
__device__ __forceinline__ float sp(float x){return log1pf(expf(x));}
__device__ __forceinline__ uint32_t smem_u32(const void* p){
    uint32_t a; asm("{ .reg .u64 t; cvta.to.shared.u64 t, %1; cvt.u32.u64 %0, t; }":"=r"(a):"l"(p)); return a;
}
__device__ __forceinline__ void ldm4(uint32_t&a0,uint32_t&a1,uint32_t&a2,uint32_t&a3,uint32_t ad){
    asm volatile("ldmatrix.sync.aligned.m8n8.x4.shared.b16 {%0,%1,%2,%3}, [%4];"
        :"=r"(a0),"=r"(a1),"=r"(a2),"=r"(a3):"r"(ad));
}
__device__ __forceinline__ void ldm2(uint32_t&b0,uint32_t&b1,uint32_t ad){
    asm volatile("ldmatrix.sync.aligned.m8n8.x2.shared.b16 {%0,%1}, [%2];"
        :"=r"(b0),"=r"(b1):"r"(ad));
}
__device__ __forceinline__ void mmabf(float* c,const uint32_t* a,uint32_t b0,uint32_t b1){
    asm volatile("mma.sync.aligned.m16n8k16.row.col.f32.bf16.bf16.f32 "
        "{%0,%1,%2,%3},{%4,%5,%6,%7},{%8,%9},{%0,%1,%2,%3};"
        :"+f"(c[0]),"+f"(c[1]),"+f"(c[2]),"+f"(c[3])
        :"r"(a[0]),"r"(a[1]),"r"(a[2]),"r"(a[3]),"r"(b0),"r"(b1));
}

// ---------- split fp32 -> bf16 hi/lo ----------
__global__ void split_k(const float* __restrict__ X,const float* __restrict__ Wq,
                        const float* __restrict__ Wk,const float* __restrict__ Wv)
{
    const int total=2048*1024+3*1024*1024;
    for(int i=blockIdx.x*blockDim.x+threadIdx.x;i<total;i+=gridDim.x*blockDim.x){
        float v; __nv_bfloat16 *ph,*pl;
        if(i<2048*1024){ v=X[i]; ph=&g_xh[i]; pl=&g_xl[i]; }
        else{ int j=i-2048*1024; int z=j>>20; int off=j&1048575;
              v=(z==0?Wq:(z==1?Wk:Wv))[off]; ph=&g_wh[j]; pl=&g_wl[j]; }
        __nv_bfloat16 h=__float2bfloat16(v);
        *ph=h; *pl=__float2bfloat16(v-__bfloat162float(h));
    }
}

// ---------- QKV via HMMA bf16 split: C[128x128] = X @ W^T ----------
#define LDA 40
#define AH_OFF 0
#define AL_OFF 10240
#define BH_OFF 20480
#define BL_OFF 30720
#define QSMB 67584

__global__ __launch_bounds__(256,2) void qkv_hmma(const float* __restrict__ logc)
{
    extern __shared__ char smc[];
    float* Cs=(float*)smc;
    const uint32_t smb=smem_u32(smc);
    const int tid=threadIdx.x, lane=tid&31, wid=tid>>5;
    const int wm=wid>>2, wn=wid&3;
    const int z=blockIdx.z, m0=blockIdx.y*128, n0=blockIdx.x*128;
    const __nv_bfloat16* __restrict__ WH=g_wh+((size_t)z<<20);
    const __nv_bfloat16* __restrict__ WL=g_wl+((size_t)z<<20);
    float acc[4][4][4]={};
    const int lr=lane&15, lc=lane>>4;
    const int l8=lane&7, lk=(lane>>3)&1;

    for(int kt=0;kt<32;++kt){
        #pragma unroll
        for(int it=0;it<4;++it){
            int idx=tid+it*256;
            int r=idx>>3, q=idx&7;
            size_t ga=(size_t)(m0+r)*1024+kt*32+q*4;
            size_t gb=(size_t)(n0+r)*1024+kt*32+q*4;
            *(uint2*)(smc+AH_OFF+(r*LDA+q*4)*2)=*(const uint2*)&g_xh[ga];
            *(uint2*)(smc+AL_OFF+(r*LDA+q*4)*2)=*(const uint2*)&g_xl[ga];
            *(uint2*)(smc+BH_OFF+(r*LDA+q*4)*2)=*(const uint2*)&WH[gb];
            *(uint2*)(smc+BL_OFF+(r*LDA+q*4)*2)=*(const uint2*)&WL[gb];
        }
        __syncthreads();
        #pragma unroll
        for(int ks=0;ks<2;++ks){
            uint32_t ah[4][4], al[4][4];
            #pragma unroll
            for(int mt=0;mt<4;++mt){
                uint32_t aa=smb+AH_OFF+((wm*64+mt*16+lr)*LDA+ks*16+lc*8)*2;
                ldm4(ah[mt][0],ah[mt][1],ah[mt][2],ah[mt][3],aa);
                ldm4(al[mt][0],al[mt][1],al[mt][2],al[mt][3],aa+(AL_OFF-AH_OFF));
            }
            #pragma unroll
            for(int nt=0;nt<4;++nt){
                uint32_t ba=smb+BH_OFF+((wn*32+nt*8+l8)*LDA+ks*16+lk*8)*2;
                uint32_t bh0,bh1,bl0,bl1;
                ldm2(bh0,bh1,ba);
                ldm2(bl0,bl1,ba+(BL_OFF-BH_OFF));
                #pragma unroll
                for(int mt=0;mt<4;++mt){
                    mmabf(acc[mt][nt],ah[mt],bh0,bh1);
                    mmabf(acc[mt][nt],al[mt],bh0,bh1);
                    mmabf(acc[mt][nt],ah[mt],bl0,bl1);
                }
            }
        }
        __syncthreads();
    }
    // stage C in smem (union with A/B tiles; mainloop ended with a sync)
    {
        int g=lane>>2, tg=lane&3;
        #pragma unroll
        for(int mt=0;mt<4;++mt){
            int r0=wm*64+mt*16+g;
            #pragma unroll
            for(int nt=0;nt<4;++nt){
                int col=wn*32+nt*8+2*tg;
                *(float2*)&Cs[r0*132+col]    =make_float2(acc[mt][nt][0],acc[mt][nt][1]);
                *(float2*)&Cs[(r0+8)*132+col]=make_float2(acc[mt][nt][2],acc[mt][nt][3]);
            }
        }
    }
    __syncthreads();
    // fused hyperbolic epilogue: one thread per (row, head-half)
    const float c_=sp(*logc), sc=sqrtf(c_);
    {
        const int half=tid>>7, row=tid&127;
        const float* rp=&Cs[row*132+half*64];
        float ss=0.f;
        #pragma unroll
        for(int j=0;j<16;++j){
            float4 v=*(const float4*)&rp[j*4];
            ss=fmaf(v.x,v.x,fmaf(v.y,v.y,fmaf(v.z,v.z,fmaf(v.w,v.w,ss))));
        }
        const int m=m0+row, b=m>>10, s=m&1023;
        const int hh=blockIdx.x*2+half, bh=b*H_+hh;
        float n=fmaxf(sqrtf(ss),EPSF), scn=sc*n, t1=tanhf(scn);
        float scale;
        if(z<2) scale=t1/scn;
        else { float th=1.f-sc*EPSF; scale=(t1<th)?1.f:(atanhf(th)/scn); }
        if(z==2){
            float4* dst=(float4*)&g_vt[((size_t)bh*S_+s)*64];
            #pragma unroll
            for(int j=0;j<16;++j){
                float4 v=*(const float4*)&rp[j*4];
                dst[j]=make_float4(v.x*scale,v.y*scale,v.z*scale,v.w*scale);
            }
        }else{
            float* __restrict__ T=(z==0)?g_qt:g_kt;
            size_t base=(size_t)bh*64*S_+s;
            #pragma unroll
            for(int j=0;j<16;++j){
                float4 v=*(const float4*)&rp[j*4];
                T[base+(size_t)(4*j+0)*S_]=v.x*scale;
                T[base+(size_t)(4*j+1)*S_]=v.y*scale;
                T[base+(size_t)(4*j+2)*S_]=v.z*scale;
                T[base+(size_t)(4*j+3)*S_]=v.w*scale;
            }
            ((z==0)?g_qns:g_kns)[bh*S_+s]=scale*scale*ss;
        }
    }
}

// ===== out-proj GEMM (fp32 FMA2, R7-validated) =====
__global__ __launch_bounds__(256,2) void out_gemm(const float* __restrict__ W,float* __restrict__ Cout)
{
    __shared__ float Asd[16*268];
    __shared__ float Bs [16*132];
    const int m0=blockIdx.y*128,n0=blockIdx.x*128,tid=threadIdx.x;
    const int tx=tid&15,ty=tid>>4;
    ull acc[8][4]={};
    const float4* A4=(const float4*)g_att; const float4* W4=(const float4*)W;
    const int ar=tid>>2,kq=tid&3;
    float4 pa0=A4[(size_t)(m0+ar)*256+kq];
    float4 pa1=A4[(size_t)(m0+ar+64)*256+kq];
    float4 pb0=W4[(size_t)(n0+ar)*256+kq];
    float4 pb1=W4[(size_t)(n0+ar+64)*256+kq];
    for(int kt=0;kt<64;++kt){
        float av0[4]={pa0.x,pa0.y,pa0.z,pa0.w};
        float av1[4]={pa1.x,pa1.y,pa1.z,pa1.w};
        float bv0[4]={pb0.x,pb0.y,pb0.z,pb0.w};
        float bv1[4]={pb1.x,pb1.y,pb1.z,pb1.w};
        #pragma unroll
        for(int c=0;c<4;++c){
            int krow=kq*4+c;
            *(ull*)&Asd[krow*268+2*ar]    =f2u(av0[c],av0[c]);
            *(ull*)&Asd[krow*268+2*ar+128]=f2u(av1[c],av1[c]);
            Bs[krow*132+ar]   =bv0[c];
            Bs[krow*132+ar+64]=bv1[c];
        }
        __syncthreads();
        if(kt<63){
            pa0=A4[(size_t)(m0+ar)*256+(kt+1)*4+kq];
            pa1=A4[(size_t)(m0+ar+64)*256+(kt+1)*4+kq];
            pb0=W4[(size_t)(n0+ar)*256+(kt+1)*4+kq];
            pb1=W4[(size_t)(n0+ar+64)*256+(kt+1)*4+kq];
        }
        #pragma unroll
        for(int kk=0;kk<16;++kk){
            ulonglong2 a0=*(const ulonglong2*)&Asd[kk*268+16*ty];
            ulonglong2 a1=*(const ulonglong2*)&Asd[kk*268+16*ty+4];
            ulonglong2 a2=*(const ulonglong2*)&Asd[kk*268+16*ty+8];
            ulonglong2 a3=*(const ulonglong2*)&Asd[kk*268+16*ty+12];
            ulonglong2 b0=*(const ulonglong2*)&Bs[kk*132+tx*4];
            ulonglong2 b1=*(const ulonglong2*)&Bs[kk*132+64+tx*4];
            ull ad[8]={a0.x,a0.y,a1.x,a1.y,a2.x,a2.y,a3.x,a3.y};
            #pragma unroll
            for(int i=0;i<8;++i){
                fma2(acc[i][0],ad[i],b0.x); fma2(acc[i][1],ad[i],b0.y);
                fma2(acc[i][2],ad[i],b1.x); fma2(acc[i][3],ad[i],b1.y);
            }
        }
        __syncthreads();
    }
    #pragma unroll
    for(int i=0;i<8;++i){
        int m=m0+ty*8+i;
        float2 c0=u2f(acc[i][0]),c1=u2f(acc[i][1]),c2=u2f(acc[i][2]),c3=u2f(acc[i][3]);
        *(float4*)&Cout[(size_t)m*D_+n0+tx*4]   =make_float4(c0.x,c0.y,c1.x,c1.y);
        *(float4*)&Cout[(size_t)m*D_+n0+64+tx*4]=make_float4(c2.x,c2.y,c3.x,c3.y);
    }
}

// ===== Attention (R7-validated) =====
#define QS0 0
#define KSD 8448
#define VSD 16896
#define PSS 25344
#define KNO 33792
#define IOYO 33856
#define ASMF 33920
#define ASMB (ASMF*4)

__global__ __launch_bounds__(256) void attn_k(const float* __restrict__ lp,
                                              const float* __restrict__ bp)
{
    extern __shared__ float sm[];
    const int bh=blockIdx.y, q0=blockIdx.x*128, tid=threadIdx.x;
    const int tx=tid&15, ty=tid>>4;
    const float c_=sp(*lp), sc=sqrtf(c_), bis=sp(*bp)/sc, tc=2.f*c_;
    const float* __restrict__ Qt=g_qt+(size_t)bh*64*S_;
    const float* __restrict__ Kt=g_kt+(size_t)bh*64*S_;
    const float* __restrict__ Vg=g_vt+(size_t)bh*S_*64;

    #pragma unroll
    for(int u=0;u<8;++u){ int idx=tid+u*256, d=idx>>5, qq=idx&31;
        *(float4*)&sm[QS0+d*132+qq*4]=*(const float4*)&Qt[(size_t)d*S_+q0+qq*4]; }

    ull qn2[4], iox2[4];
    #pragma unroll
    for(int i=0;i<4;++i){
        float a=g_qns[bh*S_+q0+ty*8+2*i], b=g_qns[bh*S_+q0+ty*8+2*i+1];
        qn2[i]=f2u(a,b);
        iox2[i]=f2u(__fdividef(1.f,1.f-c_*a),__fdividef(1.f,1.f-c_*b));
    }
    float mrow[8], lrow[8];
    #pragma unroll
    for(int r=0;r<8;++r){ mrow[r]=-INFINITY; lrow[r]=0.f; }
    ull o[4][4]={};
    const int kc0=2*tx, kc2=2*tx+32;

    for(int kt=0;kt<16;++kt){
        const int k0=kt*64;
        __syncthreads();
        #pragma unroll
        for(int u=0;u<4;++u){ int idx=tid+u*256, d=idx>>4, kq=idx&15;
            float4 kv=*(const float4*)&Kt[(size_t)d*S_+k0+kq*4];
            ull* kp=(ull*)&sm[KSD+d*132+kq*8];
            kp[0]=f2u(kv.x,kv.x); kp[1]=f2u(kv.y,kv.y);
            kp[2]=f2u(kv.z,kv.z); kp[3]=f2u(kv.w,kv.w);
            float4 vv=*(const float4*)&Vg[(size_t)(k0+d)*64+kq*4];
            ull* vp=(ull*)&sm[VSD+d*132+kq*8];
            vp[0]=f2u(vv.x,vv.x); vp[1]=f2u(vv.y,vv.y);
            vp[2]=f2u(vv.z,vv.z); vp[3]=f2u(vv.w,vv.w);
        }
        if(tid<64){ float kn=g_kns[bh*S_+k0+tid];
            sm[KNO+tid]=kn; sm[IOYO+tid]=__fdividef(1.f,1.f-c_*kn); }
        __syncthreads();

        ull s2[4][4]={};
        #pragma unroll 16
        for(int d=0;d<64;++d){
            ulonglong2 qa=*(const ulonglong2*)&sm[QS0+d*132+ty*8];
            ulonglong2 qb=*(const ulonglong2*)&sm[QS0+d*132+ty*8+4];
            ulonglong2 ka=*(const ulonglong2*)&sm[KSD+d*132+tx*4];
            ulonglong2 kb=*(const ulonglong2*)&sm[KSD+d*132+64+tx*4];
            fma2(s2[0][0],qa.x,ka.x); fma2(s2[0][1],qa.x,ka.y);
            fma2(s2[0][2],qa.x,kb.x); fma2(s2[0][3],qa.x,kb.y);
            fma2(s2[1][0],qa.y,ka.x); fma2(s2[1][1],qa.y,ka.y);
            fma2(s2[1][2],qa.y,kb.x); fma2(s2[1][3],qa.y,kb.y);
            fma2(s2[2][0],qb.x,ka.x); fma2(s2[2][1],qb.x,ka.y);
            fma2(s2[2][2],qb.x,kb.x); fma2(s2[2][3],qb.x,kb.y);
            fma2(s2[3][0],qb.y,ka.x); fma2(s2[3][1],qb.y,ka.y);
            fma2(s2[3][2],qb.y,kb.x); fma2(s2[3][3],qb.y,kb.y);
        }
        float kns[4],ioys[4];
        kns[0]=sm[KNO+kc0]; kns[1]=sm[KNO+kc0+1]; kns[2]=sm[KNO+kc2]; kns[3]=sm[KNO+kc2+1];
        ioys[0]=sm[IOYO+kc0]; ioys[1]=sm[IOYO+kc0+1]; ioys[2]=sm[IOYO+kc2]; ioys[3]=sm[IOYO+kc2+1];
        float res[8][4];
        #pragma unroll
        for(int i=0;i<4;++i){
            float2 qn=u2f(qn2[i]), iox=u2f(iox2[i]);
            #pragma unroll
            for(int c=0;c<4;++c){
                float2 dot=u2f(s2[i][c]);
                float dsq0=fmaf(-2.f,dot.x,qn.x+kns[c]);
                float tt0=fminf(iox.x*ioys[c],1.0e5f);
                float a0=fmaxf(fmaf(tc*dsq0,tt0,1.f),1.f+EPSF);
                res[2*i][c]=-bis*lg2ap(a0+sqap(fmaf(a0,a0,-1.f)));
                float dsq1=fmaf(-2.f,dot.y,qn.y+kns[c]);
                float tt1=fminf(iox.y*ioys[c],1.0e5f);
                float a1=fmaxf(fmaf(tc*dsq1,tt1,1.f),1.f+EPSF);
                res[2*i+1][c]=-bis*lg2ap(a1+sqap(fmaf(a1,a1,-1.f)));
            }
        }
        float pcorr[8];
        #pragma unroll
        for(int r=0;r<8;++r){
            float tm=fmaxf(fmaxf(res[r][0],res[r][1]),fmaxf(res[r][2],res[r][3]));
            tm=fmaxf(tm,__shfl_xor_sync(~0u,tm,1));
            tm=fmaxf(tm,__shfl_xor_sync(~0u,tm,2));
            tm=fmaxf(tm,__shfl_xor_sync(~0u,tm,4));
            tm=fmaxf(tm,__shfl_xor_sync(~0u,tm,8));
            float mn=fmaxf(mrow[r],tm);
            pcorr[r]=ex2ap(mrow[r]-mn); mrow[r]=mn;
            float ls=0.f;
            #pragma unroll
            for(int c=0;c<4;++c){ float p=ex2ap(res[r][c]-mn); res[r][c]=p; ls+=p; }
            ls+=__shfl_xor_sync(~0u,ls,1); ls+=__shfl_xor_sync(~0u,ls,2);
            ls+=__shfl_xor_sync(~0u,ls,4); ls+=__shfl_xor_sync(~0u,ls,8);
            lrow[r]=lrow[r]*pcorr[r]+ls;
        }
        #pragma unroll
        for(int i=0;i<4;++i){
            ull cr=f2u(pcorr[2*i],pcorr[2*i+1]);
            mul2(o[i][0],o[i][0],cr); mul2(o[i][1],o[i][1],cr);
            mul2(o[i][2],o[i][2],cr); mul2(o[i][3],o[i][3],cr);
        }
        #pragma unroll
        for(int i=0;i<4;++i){
            *(ull*)&sm[PSS+kc0*132    +ty*8+2*i]=f2u(res[2*i][0],res[2*i+1][0]);
            *(ull*)&sm[PSS+(kc0+1)*132+ty*8+2*i]=f2u(res[2*i][1],res[2*i+1][1]);
            *(ull*)&sm[PSS+kc2*132    +ty*8+2*i]=f2u(res[2*i][2],res[2*i+1][2]);
            *(ull*)&sm[PSS+(kc2+1)*132+ty*8+2*i]=f2u(res[2*i][3],res[2*i+1][3]);
        }
        __syncthreads();
        #pragma unroll 16
        for(int kk=0;kk<64;++kk){
            ulonglong2 pa=*(const ulonglong2*)&sm[PSS+kk*132+ty*8];
            ulonglong2 pb=*(const ulonglong2*)&sm[PSS+kk*132+ty*8+4];
            ulonglong2 va=*(const ulonglong2*)&sm[VSD+kk*132+tx*4];
            ulonglong2 vb=*(const ulonglong2*)&sm[VSD+kk*132+64+tx*4];
            fma2(o[0][0],pa.x,va.x); fma2(o[0][1],pa.x,va.y);
            fma2(o[0][2],pa.x,vb.x); fma2(o[0][3],pa.x,vb.y);
            fma2(o[1][0],pa.y,va.x); fma2(o[1][1],pa.y,va.y);
            fma2(o[1][2],pa.y,vb.x); fma2(o[1][3],pa.y,vb.y);
            fma2(o[2][0],pb.x,va.x); fma2(o[2][1],pb.x,va.y);
            fma2(o[2][2],pb.x,vb.x); fma2(o[2][3],pb.x,vb.y);
            fma2(o[3][0],pb.y,va.x); fma2(o[3][1],pb.y,va.y);
            fma2(o[3][2],pb.y,vb.x); fma2(o[3][3],pb.y,vb.y);
        }
    }
    const int b=bh>>4, hh=bh&15;
    #pragma unroll
    for(int i=0;i<4;++i){
        #pragma unroll
        for(int h=0;h<2;++h){
            int r=ty*8+2*i+h;
            float invl=__fdividef(1.f,lrow[2*i+h]);
            float2 f0=u2f(o[i][0]),f1=u2f(o[i][1]),f2=u2f(o[i][2]),f3=u2f(o[i][3]);
            float e0=(h?f0.y:f0.x)*invl, e1=(h?f1.y:f1.x)*invl;
            float e2=(h?f2.y:f2.x)*invl, e3=(h?f3.y:f3.x)*invl;
            float ss=e0*e0+e1*e1+e2*e2+e3*e3;
            ss+=__shfl_xor_sync(~0u,ss,1); ss+=__shfl_xor_sync(~0u,ss,2);
            ss+=__shfl_xor_sync(~0u,ss,4); ss+=__shfl_xor_sync(~0u,ss,8);
            float n=fmaxf(sqrtf(ss),EPSF), scn=sc*n, t1=tanhf(scn);
            float th=1.f-sc*EPSF;
            float scale=(t1<th)?1.f:(atanhf(th)/scn);
            size_t dst=(size_t)(b*S_+q0+r)*D_+hh*64;
            *(float2*)&g_att[dst+2*tx]   =make_float2(e0*scale,e1*scale);
            *(float2*)&g_att[dst+32+2*tx]=make_float2(e2*scale,e3*scale);
        }
    }
}

extern "C" void kernel_launch(void* const* d_in, const int* in_sizes, int n_in,
                              void* d_out, int out_size)
{
    (void)in_sizes;(void)n_in;(void)out_size;
    const float* x   =(const float*)d_in[0];
    const float* Wq  =(const float*)d_in[1];
    const float* Wk  =(const float*)d_in[2];
    const float* Wv  =(const float*)d_in[3];
    const float* Wo  =(const float*)d_in[4];
    const float* logc=(const float*)d_in[5];
    const float* beta=(const float*)d_in[6];
    float* out=(float*)d_out;

    cudaFuncSetAttribute(attn_k, cudaFuncAttributeMaxDynamicSharedMemorySize, ASMB);
    cudaFuncSetAttribute(qkv_hmma, cudaFuncAttributeMaxDynamicSharedMemorySize, QSMB);

    split_k<<<2048,256>>>(x,Wq,Wk,Wv);
    qkv_hmma<<<dim3(8,16,3),256,QSMB>>>(logc);
    attn_k<<<dim3(8,32),256,ASMB>>>(logc,beta);
    out_gemm<<<dim3(8,16),256>>>(Wo,out);
}

// round 12
// speedup vs baseline: 3.9307x; 1.5424x over previous
#include <cuda_runtime.h>
#include <cuda_bf16.h>
#include <math.h>
#include <stdint.h>

#define S_ 1024
#define D_ 1024
#define H_ 16
#define EPSF 1e-5f
typedef unsigned long long ull;

__device__ float g_qns[2*H_*S_];
__device__ float g_kns[2*H_*S_];
__device__ __align__(16) __nv_bfloat16 g_xh[2048*1024];
__device__ __align__(16) __nv_bfloat16 g_xl[2048*1024];
__device__ __align__(16) __nv_bfloat16 g_wh[3*1024*1024];
__device__ __align__(16) __nv_bfloat16 g_wl[3*1024*1024];
__device__ __align__(16) __nv_bfloat16 g_woh[1024*1024];
__device__ __align__(16) __nv_bfloat16 g_wol[1024*1024];
__device__ __align__(16) __nv_bfloat16 g_qh16[2*H_*1024*64];
__device__ __align__(16) __nv_bfloat16 g_ql16[2*H_*1024*64];
__device__ __align__(16) __nv_bfloat16 g_kh16[2*H_*1024*64];
__device__ __align__(16) __nv_bfloat16 g_kl16[2*H_*1024*64];
__device__ __align__(16) __nv_bfloat16 g_vth[2*H_*64*1024];   // [bh][d][s]
__device__ __align__(16) __nv_bfloat16 g_vtl[2*H_*64*1024];
__device__ __align__(16) __nv_bfloat16 g_ath[2048*1024];
__device__ __align__(16) __nv_bfloat16 g_atl[2048*1024];

__device__ __forceinline__ float sqap(float x){float r;asm("sqrt.approx.f32 %0,%1;":"=f"(r):"f"(x));return r;}
__device__ __forceinline__ float lg2ap(float x){float r;asm("lg2.approx.f32 %0,%1;":"=f"(r):"f"(x));return r;}
__device__ __forceinline__ float ex2ap(float x){float r;asm("ex2.approx.f32 %0,%1;":"=f"(r):"f"(x));return r;}
__device__ __forceinline__ float sp(float x){return log1pf(expf(x));}
__device__ __forceinline__ uint32_t smem_u32(const void* p){
    uint32_t a; asm("{ .reg .u64 t; cvta.to.shared.u64 t, %1; cvt.u32.u64 %0, t; }":"=r"(a):"l"(p)); return a;
}
__device__ __forceinline__ void ldm4(uint32_t&a0,uint32_t&a1,uint32_t&a2,uint32_t&a3,uint32_t ad){
    asm volatile("ldmatrix.sync.aligned.m8n8.x4.shared.b16 {%0,%1,%2,%3}, [%4];"
        :"=r"(a0),"=r"(a1),"=r"(a2),"=r"(a3):"r"(ad));
}
__device__ __forceinline__ void ldm2(uint32_t&b0,uint32_t&b1,uint32_t ad){
    asm volatile("ldmatrix.sync.aligned.m8n8.x2.shared.b16 {%0,%1}, [%2];"
        :"=r"(b0),"=r"(b1):"r"(ad));
}
__device__ __forceinline__ void mmabf(float* c,const uint32_t* a,uint32_t b0,uint32_t b1){
    asm volatile("mma.sync.aligned.m16n8k16.row.col.f32.bf16.bf16.f32 "
        "{%0,%1,%2,%3},{%4,%5,%6,%7},{%8,%9},{%0,%1,%2,%3};"
        :"+f"(c[0]),"+f"(c[1]),"+f"(c[2]),"+f"(c[3])
        :"r"(a[0]),"r"(a[1]),"r"(a[2]),"r"(a[3]),"r"(b0),"r"(b1));
}
__device__ __forceinline__ void bfsplit(float v,__nv_bfloat16&h,__nv_bfloat16&l){
    h=__float2bfloat16(v); l=__float2bfloat16(v-__bfloat162float(h));
}

// ---------- split fp32 -> bf16 hi/lo (X, Wq, Wk, Wv, Wo) ----------
__global__ void split_k(const float* __restrict__ X,const float* __restrict__ Wq,
                        const float* __restrict__ Wk,const float* __restrict__ Wv,
                        const float* __restrict__ Wo)
{
    const int total=2097152+4194304;
    for(int i=blockIdx.x*blockDim.x+threadIdx.x;i<total;i+=gridDim.x*blockDim.x){
        float v; __nv_bfloat16 *ph,*pl;
        if(i<2097152){ v=X[i]; ph=&g_xh[i]; pl=&g_xl[i]; }
        else{
            int j=i-2097152;
            if(j<3145728){ int z=j>>20, off=j&1048575;
                v=(z==0?Wq:(z==1?Wk:Wv))[off]; ph=&g_wh[j]; pl=&g_wl[j]; }
            else{ int off=j-3145728; v=Wo[off]; ph=&g_woh[off]; pl=&g_wol[off]; }
        }
        bfsplit(v,*ph,*pl);
    }
}

// ---------- QKV via HMMA bf16 split: C[128x128] = X @ W^T ----------
#define LDA 40
#define AH_OFF 0
#define AL_OFF 10240
#define BH_OFF 20480
#define BL_OFF 30720
#define QSMB 67584

__global__ __launch_bounds__(256,2) void qkv_hmma(const float* __restrict__ logc)
{
    extern __shared__ char smc[];
    float* Cs=(float*)smc;
    const uint32_t smb=smem_u32(smc);
    const int tid=threadIdx.x, lane=tid&31, wid=tid>>5;
    const int wm=wid>>2, wn=wid&3;
    const int z=blockIdx.z, m0=blockIdx.y*128, n0=blockIdx.x*128;
    const __nv_bfloat16* __restrict__ WH=g_wh+((size_t)z<<20);
    const __nv_bfloat16* __restrict__ WL=g_wl+((size_t)z<<20);
    float acc[4][4][4]={};
    const int lr=lane&15, lc=lane>>4;
    const int l8=lane&7, lk=(lane>>3)&1;

    for(int kt=0;kt<32;++kt){
        #pragma unroll
        for(int it=0;it<4;++it){
            int idx=tid+it*256;
            int r=idx>>3, q=idx&7;
            size_t ga=(size_t)(m0+r)*1024+kt*32+q*4;
            size_t gb=(size_t)(n0+r)*1024+kt*32+q*4;
            *(uint2*)(smc+AH_OFF+(r*LDA+q*4)*2)=*(const uint2*)&g_xh[ga];
            *(uint2*)(smc+AL_OFF+(r*LDA+q*4)*2)=*(const uint2*)&g_xl[ga];
            *(uint2*)(smc+BH_OFF+(r*LDA+q*4)*2)=*(const uint2*)&WH[gb];
            *(uint2*)(smc+BL_OFF+(r*LDA+q*4)*2)=*(const uint2*)&WL[gb];
        }
        __syncthreads();
        #pragma unroll
        for(int ks=0;ks<2;++ks){
            uint32_t ah[4][4], al[4][4];
            #pragma unroll
            for(int mt=0;mt<4;++mt){
                uint32_t aa=smb+AH_OFF+((wm*64+mt*16+lr)*LDA+ks*16+lc*8)*2;
                ldm4(ah[mt][0],ah[mt][1],ah[mt][2],ah[mt][3],aa);
                ldm4(al[mt][0],al[mt][1],al[mt][2],al[mt][3],aa+(AL_OFF-AH_OFF));
            }
            #pragma unroll
            for(int nt=0;nt<4;++nt){
                uint32_t ba=smb+BH_OFF+((wn*32+nt*8+l8)*LDA+ks*16+lk*8)*2;
                uint32_t bh0,bh1,bl0,bl1;
                ldm2(bh0,bh1,ba);
                ldm2(bl0,bl1,ba+(BL_OFF-BH_OFF));
                #pragma unroll
                for(int mt=0;mt<4;++mt){
                    mmabf(acc[mt][nt],ah[mt],bh0,bh1);
                    mmabf(acc[mt][nt],al[mt],bh0,bh1);
                    mmabf(acc[mt][nt],ah[mt],bl0,bl1);
                }
            }
        }
        __syncthreads();
    }
    {
        int g=lane>>2, tg=lane&3;
        #pragma unroll
        for(int mt=0;mt<4;++mt){
            int r0=wm*64+mt*16+g;
            #pragma unroll
            for(int nt=0;nt<4;++nt){
                int col=wn*32+nt*8+2*tg;
                *(float2*)&Cs[r0*132+col]    =make_float2(acc[mt][nt][0],acc[mt][nt][1]);
                *(float2*)&Cs[(r0+8)*132+col]=make_float2(acc[mt][nt][2],acc[mt][nt][3]);
            }
        }
    }
    __syncthreads();
    // fused hyperbolic epilogue, bf16 hi/lo outputs
    const float c_=sp(*logc), sc=sqrtf(c_);
    {
        const int half=tid>>7, row=tid&127;
        const float* rp=&Cs[row*132+half*64];
        float ss=0.f;
        #pragma unroll
        for(int j=0;j<16;++j){
            float4 v=*(const float4*)&rp[j*4];
            ss=fmaf(v.x,v.x,fmaf(v.y,v.y,fmaf(v.z,v.z,fmaf(v.w,v.w,ss))));
        }
        const int m=m0+row, b=m>>10, s=m&1023;
        const int hh=blockIdx.x*2+half, bh=b*H_+hh;
        float n=fmaxf(sqrtf(ss),EPSF), scn=sc*n, t1=tanhf(scn);
        float scale;
        if(z<2) scale=t1/scn;
        else { float th=1.f-sc*EPSF; scale=(t1<th)?1.f:(atanhf(th)/scn); }
        if(z==2){
            // store V transposed [bh][d][s], bf16 hi/lo
            #pragma unroll
            for(int j=0;j<64;++j){
                __nv_bfloat16 h,l; bfsplit(rp[j]*scale,h,l);
                g_vth[((size_t)bh*64+j)*1024+s]=h;
                g_vtl[((size_t)bh*64+j)*1024+s]=l;
            }
        }else{
            __nv_bfloat16* __restrict__ TH=(z==0)?g_qh16:g_kh16;
            __nv_bfloat16* __restrict__ TL=(z==0)?g_ql16:g_kl16;
            size_t base=((size_t)bh*1024+s)*64;
            #pragma unroll
            for(int j=0;j<16;++j){
                float4 v=*(const float4*)&rp[j*4];
                __nv_bfloat16 h0,l0,h1,l1,h2,l2,h3,l3;
                bfsplit(v.x*scale,h0,l0); bfsplit(v.y*scale,h1,l1);
                bfsplit(v.z*scale,h2,l2); bfsplit(v.w*scale,h3,l3);
                *(__nv_bfloat162*)&TH[base+j*4]  =__nv_bfloat162(h0,h1);
                *(__nv_bfloat162*)&TH[base+j*4+2]=__nv_bfloat162(h2,h3);
                *(__nv_bfloat162*)&TL[base+j*4]  =__nv_bfloat162(l0,l1);
                *(__nv_bfloat162*)&TL[base+j*4+2]=__nv_bfloat162(l2,l3);
            }
            ((z==0)?g_qns:g_kns)[bh*1024+s]=scale*scale*ss;
        }
    }
}

// ---------- Attention via HMMA: 128q x 64k tiles, smem-staged scores ----------
#define LQ 72
#define SST 72
#define QH_B 0
#define QL_B 18432
#define KH_B 36864
#define KL_B 46080
#define VH_B 55296
#define VL_B 64512
#define S_B  73728
#define PH_B 110592
#define PL_B 129024
#define PC_B 147456
#define LR_B 147968
#define KN_B 148480
#define IOY_B 148736
#define ATSMB 148992

__global__ __launch_bounds__(256) void attn_hmma(const float* __restrict__ lp,
                                                 const float* __restrict__ bp)
{
    extern __shared__ char smc[];
    const uint32_t smb=smem_u32(smc);
    float* Sf =(float*)(smc+S_B);
    float* PCf=(float*)(smc+PC_B);
    float* LRf=(float*)(smc+LR_B);
    float* KNf=(float*)(smc+KN_B);
    float* IOYf=(float*)(smc+IOY_B);
    const int tid=threadIdx.x, lane=tid&31, wid=tid>>5;
    const int bh=blockIdx.y, q0=blockIdx.x*128;
    const float c_=sp(*lp), sc=sqrtf(c_), bis=sp(*bp)/sc, tc=2.f*c_;

    // stage Q (rows q, cols d) bf16 hi/lo
    {
        const __nv_bfloat16* Qh=&g_qh16[((size_t)bh*1024+q0)*64];
        const __nv_bfloat16* Ql=&g_ql16[((size_t)bh*1024+q0)*64];
        #pragma unroll
        for(int it=0;it<8;++it){
            int idx=tid+it*256, r=idx>>4, q=idx&15;
            *(uint2*)(smc+QH_B+(r*LQ+q*4)*2)=*(const uint2*)&Qh[r*64+q*4];
            *(uint2*)(smc+QL_B+(r*LQ+q*4)*2)=*(const uint2*)&Ql[r*64+q*4];
        }
    }
    const int srow=tid>>1, shalf=tid&1;
    float qn=g_qns[bh*1024+q0+srow];
    float iox=__fdividef(1.f,1.f-c_*qn);
    float mold=-INFINITY, lhalf=0.f;
    float oacc[8][4]={};
    const int lr=lane&15, lc=lane>>4, l8=lane&7, lk=(lane>>3)&1;
    const int g=lane>>2, tg=lane&3;

    for(int kt=0;kt<16;++kt){
        const int k0=kt*64;
        __syncthreads();   // prev-iter P/V consumers done
        {
            const __nv_bfloat16* Kh=&g_kh16[((size_t)bh*1024+k0)*64];
            const __nv_bfloat16* Kl=&g_kl16[((size_t)bh*1024+k0)*64];
            const __nv_bfloat16* Vh=&g_vth[(size_t)bh*64*1024];
            const __nv_bfloat16* Vl=&g_vtl[(size_t)bh*64*1024];
            #pragma unroll
            for(int it=0;it<4;++it){
                int idx=tid+it*256, r=idx>>4, q=idx&15;
                *(uint2*)(smc+KH_B+(r*LQ+q*4)*2)=*(const uint2*)&Kh[r*64+q*4];
                *(uint2*)(smc+KL_B+(r*LQ+q*4)*2)=*(const uint2*)&Kl[r*64+q*4];
                *(uint2*)(smc+VH_B+(r*LQ+q*4)*2)=*(const uint2*)&Vh[(size_t)r*1024+k0+q*4];
                *(uint2*)(smc+VL_B+(r*LQ+q*4)*2)=*(const uint2*)&Vl[(size_t)r*1024+k0+q*4];
            }
            if(tid<64){ float kn=g_kns[bh*1024+k0+tid];
                KNf[tid]=kn; IOYf[tid]=__fdividef(1.f,1.f-c_*kn); }
        }
        __syncthreads();
        // S = Q K^T  (warp wid owns q-rows 16*wid..+15)
        {
            float sacc[8][4]={};
            #pragma unroll
            for(int ks=0;ks<4;++ks){
                uint32_t ah[4],al[4];
                uint32_t aa=smb+QH_B+((16*wid+lr)*LQ+ks*16+lc*8)*2;
                ldm4(ah[0],ah[1],ah[2],ah[3],aa);
                ldm4(al[0],al[1],al[2],al[3],aa+(QL_B-QH_B));
                #pragma unroll
                for(int nt=0;nt<8;++nt){
                    uint32_t ba=smb+KH_B+((nt*8+l8)*LQ+ks*16+lk*8)*2;
                    uint32_t kh0,kh1,kl0,kl1;
                    ldm2(kh0,kh1,ba);
                    ldm2(kl0,kl1,ba+(KL_B-KH_B));
                    mmabf(sacc[nt],ah,kh0,kh1);
                    mmabf(sacc[nt],al,kh0,kh1);
                    mmabf(sacc[nt],ah,kl0,kl1);
                }
            }
            #pragma unroll
            for(int nt=0;nt<8;++nt){
                *(float2*)&Sf[(16*wid+g)*SST+nt*8+2*tg]  =make_float2(sacc[nt][0],sacc[nt][1]);
                *(float2*)&Sf[(16*wid+8+g)*SST+nt*8+2*tg]=make_float2(sacc[nt][2],sacc[nt][3]);
            }
        }
        __syncthreads();
        // score + online softmax (2 threads per q-row)
        {
            float sv[32];
            const float* sp_=&Sf[srow*SST+shalf*32];
            #pragma unroll
            for(int j=0;j<8;++j){
                float4 s4=*(const float4*)&sp_[j*4];
                float v[4]={s4.x,s4.y,s4.z,s4.w};
                #pragma unroll
                for(int u=0;u<4;++u){
                    int t=shalf*32+j*4+u;
                    float dsq=fmaf(-2.f,v[u],qn+KNf[t]);
                    float tt=fminf(iox*IOYf[t],1.0e5f);
                    float a0=fmaxf(fmaf(tc*dsq,tt,1.f),1.f+EPSF);
                    sv[j*4+u]=-bis*lg2ap(a0+sqap(fmaf(a0,a0,-1.f)));
                }
            }
            float tm=-INFINITY;
            #pragma unroll
            for(int j=0;j<32;++j) tm=fmaxf(tm,sv[j]);
            tm=fmaxf(tm,__shfl_xor_sync(~0u,tm,1));
            float mn=fmaxf(mold,tm);
            float pc=ex2ap(mold-mn);
            mold=mn;
            float ls=0.f;
            #pragma unroll
            for(int j=0;j<32;++j){ float p=ex2ap(sv[j]-mn); sv[j]=p; ls+=p; }
            lhalf=lhalf*pc+ls;
            if(shalf==0) PCf[srow]=pc;
            #pragma unroll
            for(int j=0;j<16;++j){
                __nv_bfloat16 h0,l0,h1,l1;
                bfsplit(sv[2*j],h0,l0); bfsplit(sv[2*j+1],h1,l1);
                int col=shalf*32+2*j;
                *(__nv_bfloat162*)(smc+PH_B+(srow*LQ+col)*2)=__nv_bfloat162(h0,h1);
                *(__nv_bfloat162*)(smc+PL_B+(srow*LQ+col)*2)=__nv_bfloat162(l0,l1);
            }
        }
        __syncthreads();
        // O = O*pc + P V
        {
            float pc0=PCf[16*wid+g], pc8=PCf[16*wid+8+g];
            #pragma unroll
            for(int nt=0;nt<8;++nt){
                oacc[nt][0]*=pc0; oacc[nt][1]*=pc0;
                oacc[nt][2]*=pc8; oacc[nt][3]*=pc8;
            }
            #pragma unroll
            for(int ks=0;ks<4;++ks){
                uint32_t ph[4],pl[4];
                uint32_t pa=smb+PH_B+((16*wid+lr)*LQ+ks*16+lc*8)*2;
                ldm4(ph[0],ph[1],ph[2],ph[3],pa);
                ldm4(pl[0],pl[1],pl[2],pl[3],pa+(PL_B-PH_B));
                #pragma unroll
                for(int nt=0;nt<8;++nt){
                    uint32_t va=smb+VH_B+((nt*8+l8)*LQ+ks*16+lk*8)*2;
                    uint32_t vh0,vh1,vl0,vl1;
                    ldm2(vh0,vh1,va);
                    ldm2(vl0,vl1,va+(VL_B-VH_B));
                    mmabf(oacc[nt],ph,vh0,vh1);
                    mmabf(oacc[nt],pl,vh0,vh1);
                    mmabf(oacc[nt],ph,vl0,vl1);
                }
            }
        }
    }
    // final 1/l
    {
        float lf=lhalf+__shfl_xor_sync(~0u,lhalf,1);
        if(shalf==0) LRf[srow]=__fdividef(1.f,lf);
    }
    __syncthreads();
    // finalize: /l, head transform, write bf16 hi/lo concat
    {
        float i0=LRf[16*wid+g], i8=LRf[16*wid+8+g];
        float ss0=0.f, ss8=0.f;
        #pragma unroll
        for(int nt=0;nt<8;++nt){
            float e0=oacc[nt][0]*i0, e1=oacc[nt][1]*i0;
            float e2=oacc[nt][2]*i8, e3=oacc[nt][3]*i8;
            ss0=fmaf(e0,e0,fmaf(e1,e1,ss0));
            ss8=fmaf(e2,e2,fmaf(e3,e3,ss8));
        }
        ss0+=__shfl_xor_sync(~0u,ss0,1); ss0+=__shfl_xor_sync(~0u,ss0,2);
        ss8+=__shfl_xor_sync(~0u,ss8,1); ss8+=__shfl_xor_sync(~0u,ss8,2);
        const float th=1.f-sc*EPSF;
        float n0=fmaxf(sqrtf(ss0),EPSF), scn0=sc*n0, t10=tanhf(scn0);
        float sc0=(t10<th)?i0:(atanhf(th)/scn0)*i0;
        float n8=fmaxf(sqrtf(ss8),EPSF), scn8=sc*n8, t18=tanhf(scn8);
        float sc8=(t18<th)?i8:(atanhf(th)/scn8)*i8;
        const int b=bh>>4, hh=bh&15;
        const int s0g=q0+16*wid+g, s8g=s0g+8;
        #pragma unroll
        for(int nt=0;nt<8;++nt){
            int col=hh*64+nt*8+2*tg;
            __nv_bfloat16 h0,l0,h1,l1;
            bfsplit(oacc[nt][0]*sc0,h0,l0); bfsplit(oacc[nt][1]*sc0,h1,l1);
            *(__nv_bfloat162*)&g_ath[((size_t)(b*1024+s0g))*1024+col]=__nv_bfloat162(h0,h1);
            *(__nv_bfloat162*)&g_atl[((size_t)(b*1024+s0g))*1024+col]=__nv_bfloat162(l0,l1);
            bfsplit(oacc[nt][2]*sc8,h0,l0); bfsplit(oacc[nt][3]*sc8,h1,l1);
            *(__nv_bfloat162*)&g_ath[((size_t)(b*1024+s8g))*1024+col]=__nv_bfloat162(h0,h1);
            *(__nv_bfloat162*)&g_atl[((size_t)(b*1024+s8g))*1024+col]=__nv_bfloat162(l0,l1);
        }
    }
}

// ---------- out-proj via HMMA: out = att @ Wo^T ----------
__global__ __launch_bounds__(256,2) void out_hmma(float* __restrict__ Cout)
{
    extern __shared__ char smc[];
    float* Cs=(float*)smc;
    const uint32_t smb=smem_u32(smc);
    const int tid=threadIdx.x, lane=tid&31, wid=tid>>5;
    const int wm=wid>>2, wn=wid&3;
    const int m0=blockIdx.y*128, n0=blockIdx.x*128;
    float acc[4][4][4]={};
    const int lr=lane&15, lc=lane>>4;
    const int l8=lane&7, lk=(lane>>3)&1;

    for(int kt=0;kt<32;++kt){
        #pragma unroll
        for(int it=0;it<4;++it){
            int idx=tid+it*256;
            int r=idx>>3, q=idx&7;
            size_t ga=(size_t)(m0+r)*1024+kt*32+q*4;
            size_t gb=(size_t)(n0+r)*1024+kt*32+q*4;
            *(uint2*)(smc+AH_OFF+(r*LDA+q*4)*2)=*(const uint2*)&g_ath[ga];
            *(uint2*)(smc+AL_OFF+(r*LDA+q*4)*2)=*(const uint2*)&g_atl[ga];
            *(uint2*)(smc+BH_OFF+(r*LDA+q*4)*2)=*(const uint2*)&g_woh[gb];
            *(uint2*)(smc+BL_OFF+(r*LDA+q*4)*2)=*(const uint2*)&g_wol[gb];
        }
        __syncthreads();
        #pragma unroll
        for(int ks=0;ks<2;++ks){
            uint32_t ah[4][4], al[4][4];
            #pragma unroll
            for(int mt=0;mt<4;++mt){
                uint32_t aa=smb+AH_OFF+((wm*64+mt*16+lr)*LDA+ks*16+lc*8)*2;
                ldm4(ah[mt][0],ah[mt][1],ah[mt][2],ah[mt][3],aa);
                ldm4(al[mt][0],al[mt][1],al[mt][2],al[mt][3],aa+(AL_OFF-AH_OFF));
            }
            #pragma unroll
            for(int nt=0;nt<4;++nt){
                uint32_t ba=smb+BH_OFF+((wn*32+nt*8+l8)*LDA+ks*16+lk*8)*2;
                uint32_t bh0,bh1,bl0,bl1;
                ldm2(bh0,bh1,ba);
                ldm2(bl0,bl1,ba+(BL_OFF-BH_OFF));
                #pragma unroll
                for(int mt=0;mt<4;++mt){
                    mmabf(acc[mt][nt],ah[mt],bh0,bh1);
                    mmabf(acc[mt][nt],al[mt],bh0,bh1);
                    mmabf(acc[mt][nt],ah[mt],bl0,bl1);
                }
            }
        }
        __syncthreads();
    }
    {
        int g=lane>>2, tg=lane&3;
        #pragma unroll
        for(int mt=0;mt<4;++mt){
            int r0=wm*64+mt*16+g;
            #pragma unroll
            for(int nt=0;nt<4;++nt){
                int col=wn*32+nt*8+2*tg;
                *(float2*)&Cs[r0*132+col]    =make_float2(acc[mt][nt][0],acc[mt][nt][1]);
                *(float2*)&Cs[(r0+8)*132+col]=make_float2(acc[mt][nt][2],acc[mt][nt][3]);
            }
        }
    }
    __syncthreads();
    {
        const int half=tid>>7, row=tid&127;
        const float* rp=&Cs[row*132+half*64];
        float* dst=&Cout[(size_t)(m0+row)*1024+n0+half*64];
        #pragma unroll
        for(int j=0;j<16;++j) *(float4*)&dst[j*4]=*(const float4*)&rp[j*4];
    }
}

extern "C" void kernel_launch(void* const* d_in, const int* in_sizes, int n_in,
                              void* d_out, int out_size)
{
    (void)in_sizes;(void)n_in;(void)out_size;
    const float* x   =(const float*)d_in[0];
    const float* Wq  =(const float*)d_in[1];
    const float* Wk  =(const float*)d_in[2];
    const float* Wv  =(const float*)d_in[3];
    const float* Wo  =(const float*)d_in[4];
    const float* logc=(const float*)d_in[5];
    const float* beta=(const float*)d_in[6];
    float* out=(float*)d_out;

    cudaFuncSetAttribute(qkv_hmma, cudaFuncAttributeMaxDynamicSharedMemorySize, QSMB);
    cudaFuncSetAttribute(attn_hmma, cudaFuncAttributeMaxDynamicSharedMemorySize, ATSMB);
    cudaFuncSetAttribute(out_hmma, cudaFuncAttributeMaxDynamicSharedMemorySize, QSMB);

    split_k<<<2048,256>>>(x,Wq,Wk,Wv,Wo);
    qkv_hmma<<<dim3(8,16,3),256,QSMB>>>(logc);
    attn_hmma<<<dim3(8,32),256,ATSMB>>>(logc,beta);
    out_hmma<<<dim3(8,16),256,QSMB>>>(out);
}

// round 15
// speedup vs baseline: 4.3374x; 1.1034x over previous
#include <cuda_runtime.h>
#include <cuda_bf16.h>
#include <math.h>
#include <stdint.h>

#define S_ 1024
#define D_ 1024
#define H_ 16
#define EPSF 1e-5f
typedef unsigned long long ull;

__device__ float g_qns[2*H_*S_];
__device__ float g_kns[2*H_*S_];
__device__ __align__(16) __nv_bfloat16 g_xh[2048*1024];
__device__ __align__(16) __nv_bfloat16 g_xl[2048*1024];
__device__ __align__(16) __nv_bfloat16 g_wh[3*1024*1024];
__device__ __align__(16) __nv_bfloat16 g_wl[3*1024*1024];
__device__ __align__(16) __nv_bfloat16 g_woh[1024*1024];
__device__ __align__(16) __nv_bfloat16 g_wol[1024*1024];
__device__ __align__(16) __nv_bfloat16 g_qh16[2*H_*1024*64];
__device__ __align__(16) __nv_bfloat16 g_ql16[2*H_*1024*64];
__device__ __align__(16) __nv_bfloat16 g_kh16[2*H_*1024*64];
__device__ __align__(16) __nv_bfloat16 g_kl16[2*H_*1024*64];
__device__ __align__(16) __nv_bfloat16 g_vth[2*H_*64*1024];   // [bh][d][s]
__device__ __align__(16) __nv_bfloat16 g_vtl[2*H_*64*1024];
__device__ __align__(16) __nv_bfloat16 g_ath[2048*1024];
__device__ __align__(16) __nv_bfloat16 g_atl[2048*1024];

__device__ __forceinline__ float sqap(float x){float r;asm("sqrt.approx.f32 %0,%1;":"=f"(r):"f"(x));return r;}
__device__ __forceinline__ float lg2ap(float x){float r;asm("lg2.approx.f32 %0,%1;":"=f"(r):"f"(x));return r;}
__device__ __forceinline__ float ex2ap(float x){float r;asm("ex2.approx.f32 %0,%1;":"=f"(r):"f"(x));return r;}
__device__ __forceinline__ float sp(float x){return log1pf(expf(x));}
__device__ __forceinline__ uint32_t smem_u32(const void* p){
    uint32_t a; asm("{ .reg .u64 t; cvta.to.shared.u64 t, %1; cvt.u32.u64 %0, t; }":"=r"(a):"l"(p)); return a;
}
__device__ __forceinline__ void ldm4(uint32_t&a0,uint32_t&a1,uint32_t&a2,uint32_t&a3,uint32_t ad){
    asm volatile("ldmatrix.sync.aligned.m8n8.x4.shared.b16 {%0,%1,%2,%3}, [%4];"
        :"=r"(a0),"=r"(a1),"=r"(a2),"=r"(a3):"r"(ad));
}
__device__ __forceinline__ void ldm2(uint32_t&b0,uint32_t&b1,uint32_t ad){
    asm volatile("ldmatrix.sync.aligned.m8n8.x2.shared.b16 {%0,%1}, [%2];"
        :"=r"(b0),"=r"(b1):"r"(ad));
}
__device__ __forceinline__ void mmabf(float* c,const uint32_t* a,uint32_t b0,uint32_t b1){
    asm volatile("mma.sync.aligned.m16n8k16.row.col.f32.bf16.bf16.f32 "
        "{%0,%1,%2,%3},{%4,%5,%6,%7},{%8,%9},{%0,%1,%2,%3};"
        :"+f"(c[0]),"+f"(c[1]),"+f"(c[2]),"+f"(c[3])
        :"r"(a[0]),"r"(a[1]),"r"(a[2]),"r"(a[3]),"r"(b0),"r"(b1));
}
__device__ __forceinline__ void bfsplit(float v,__nv_bfloat16&h,__nv_bfloat16&l){
    h=__float2bfloat16(v); l=__float2bfloat16(v-__bfloat162float(h));
}
__device__ __forceinline__ void cpa16(uint32_t sa,const void* g){
    asm volatile("cp.async.cg.shared.global [%0], [%1], 16;"::"r"(sa),"l"(g):"memory");
}
__device__ __forceinline__ void cpcommit(){ asm volatile("cp.async.commit_group;":::"memory"); }
template<int N> __device__ __forceinline__ void cpwait(){ asm volatile("cp.async.wait_group %0;"::"n"(N):"memory"); }

// ---------- split fp32 -> bf16 hi/lo (X, Wq, Wk, Wv, Wo) ----------
__global__ void split_k(const float* __restrict__ X,const float* __restrict__ Wq,
                        const float* __restrict__ Wk,const float* __restrict__ Wv,
                        const float* __restrict__ Wo)
{
    const int total=2097152+4194304;
    for(int i=blockIdx.x*blockDim.x+threadIdx.x;i<total;i+=gridDim.x*blockDim.x){
        float v; __nv_bfloat16 *ph,*pl;
        if(i<2097152){ v=X[i]; ph=&g_xh[i]; pl=&g_xl[i]; }
        else{
            int j=i-2097152;
            if(j<3145728){ int z=j>>20, off=j&1048575;
                v=(z==0?Wq:(z==1?Wk:Wv))[off]; ph=&g_wh[j]; pl=&g_wl[j]; }
            else{ int off=j-3145728; v=Wo[off]; ph=&g_woh[off]; pl=&g_wol[off]; }
        }
        bfsplit(v,*ph,*pl);
    }
}

// ---------- QKV / out-proj via HMMA bf16 split, cp.async double-buffer ----------
#define LDA 40
#define TILE_B 40960           // 4 arrays x 10240 per buffer
#define ARR_B  10240
#define QSMB   81920           // 2 buffers (Cs 67584 unioned at base)

// generic 128x128 GEMM mainloop: C = A @ B^T (A rows m0, B rows n0, K=1024)
template<typename EPI>
__device__ __forceinline__ void hmma_gemm_128(
    char* smc,const __nv_bfloat16* AH,const __nv_bfloat16* AL,
    const __nv_bfloat16* BH,const __nv_bfloat16* BL,
    int m0,int n0,EPI epi)
{
    float* Cs=(float*)smc;
    const uint32_t smb=smem_u32(smc);
    const int tid=threadIdx.x, lane=tid&31, wid=tid>>5;
    const int wm=wid>>2, wn=wid&3;
    float acc[4][4][4]={};
    const int lr=lane&15, lc=lane>>4;
    const int l8=lane&7, lk=(lane>>3)&1;

    const __nv_bfloat16* gbase[4]={AH,AL,BH,BL};
    const int rowoff[4]={m0,m0,n0,n0};

    // prologue: issue tile 0
    {
        char* bb=smc;
        #pragma unroll
        for(int it=0;it<8;++it){
            int idx=tid+it*256, arr=idx>>9, ch=idx&511, r=ch>>2, q=ch&3;
            cpa16(smem_u32(bb+arr*ARR_B+(r*LDA+q*8)*2),
                  gbase[arr]+(size_t)(rowoff[arr]+r)*1024+q*8);
        }
        cpcommit();
    }
    for(int kt=0;kt<32;++kt){
        if(kt<31){
            char* bb=smc+((kt+1)&1)*TILE_B;
            #pragma unroll
            for(int it=0;it<8;++it){
                int idx=tid+it*256, arr=idx>>9, ch=idx&511, r=ch>>2, q=ch&3;
                cpa16(smem_u32(bb+arr*ARR_B+(r*LDA+q*8)*2),
                      gbase[arr]+(size_t)(rowoff[arr]+r)*1024+(kt+1)*32+q*8);
            }
            cpcommit();
            cpwait<1>();
        } else cpwait<0>();
        __syncthreads();
        const uint32_t bb=smb+(kt&1)*TILE_B;
        #pragma unroll
        for(int ks=0;ks<2;++ks){
            uint32_t ah[4][4], al[4][4];
            #pragma unroll
            for(int mt=0;mt<4;++mt){
                uint32_t aa=bb+((wm*64+mt*16+lr)*LDA+ks*16+lc*8)*2;
                ldm4(ah[mt][0],ah[mt][1],ah[mt][2],ah[mt][3],aa);
                ldm4(al[mt][0],al[mt][1],al[mt][2],al[mt][3],aa+ARR_B);
            }
            #pragma unroll
            for(int nt=0;nt<4;++nt){
                uint32_t ba=bb+2*ARR_B+((wn*32+nt*8+l8)*LDA+ks*16+lk*8)*2;
                uint32_t bh0,bh1,bl0,bl1;
                ldm2(bh0,bh1,ba);
                ldm2(bl0,bl1,ba+ARR_B);
                #pragma unroll
                for(int mt=0;mt<4;++mt){
                    mmabf(acc[mt][nt],ah[mt],bh0,bh1);
                    mmabf(acc[mt][nt],al[mt],bh0,bh1);
                    mmabf(acc[mt][nt],ah[mt],bl0,bl1);
                }
            }
        }
        __syncthreads();
    }
    {
        int g=lane>>2, tg=lane&3;
        #pragma unroll
        for(int mt=0;mt<4;++mt){
            int r0=wm*64+mt*16+g;
            #pragma unroll
            for(int nt=0;nt<4;++nt){
                int col=wn*32+nt*8+2*tg;
                *(float2*)&Cs[r0*132+col]    =make_float2(acc[mt][nt][0],acc[mt][nt][1]);
                *(float2*)&Cs[(r0+8)*132+col]=make_float2(acc[mt][nt][2],acc[mt][nt][3]);
            }
        }
    }
    __syncthreads();
    epi(Cs);
}

__global__ __launch_bounds__(256,2) void qkv_hmma(const float* __restrict__ logc)
{
    extern __shared__ char smc[];
    const int z=blockIdx.z, m0=blockIdx.y*128, n0=blockIdx.x*128;
    const __nv_bfloat16* WH=g_wh+((size_t)z<<20);
    const __nv_bfloat16* WL=g_wl+((size_t)z<<20);
    const float c_=sp(*logc), sc=sqrtf(c_);
    const int tid=threadIdx.x;
    hmma_gemm_128(smc,g_xh,g_xl,WH,WL,m0,n0,[&](float* Cs){
        const int half=tid>>7, row=tid&127;
        const float* rp=&Cs[row*132+half*64];
        float ss=0.f;
        #pragma unroll
        for(int j=0;j<16;++j){
            float4 v=*(const float4*)&rp[j*4];
            ss=fmaf(v.x,v.x,fmaf(v.y,v.y,fmaf(v.z,v.z,fmaf(v.w,v.w,ss))));
        }
        const int m=m0+row, b=m>>10, s=m&1023;
        const int hh=blockIdx.x*2+half, bh=b*H_+hh;
        float n=fmaxf(sqrtf(ss),EPSF), scn=sc*n, t1=tanhf(scn);
        float scale;
        if(z<2) scale=t1/scn;
        else { float th=1.f-sc*EPSF; scale=(t1<th)?1.f:(atanhf(th)/scn); }
        if(z==2){
            #pragma unroll
            for(int j=0;j<64;++j){
                __nv_bfloat16 h,l; bfsplit(rp[j]*scale,h,l);
                g_vth[((size_t)bh*64+j)*1024+s]=h;
                g_vtl[((size_t)bh*64+j)*1024+s]=l;
            }
        }else{
            __nv_bfloat16* TH=(z==0)?g_qh16:g_kh16;
            __nv_bfloat16* TL=(z==0)?g_ql16:g_kl16;
            size_t base=((size_t)bh*1024+s)*64;
            #pragma unroll
            for(int j=0;j<16;++j){
                float4 v=*(const float4*)&rp[j*4];
                __nv_bfloat16 h0,l0,h1,l1,h2,l2,h3,l3;
                bfsplit(v.x*scale,h0,l0); bfsplit(v.y*scale,h1,l1);
                bfsplit(v.z*scale,h2,l2); bfsplit(v.w*scale,h3,l3);
                *(__nv_bfloat162*)&TH[base+j*4]  =__nv_bfloat162(h0,h1);
                *(__nv_bfloat162*)&TH[base+j*4+2]=__nv_bfloat162(h2,h3);
                *(__nv_bfloat162*)&TL[base+j*4]  =__nv_bfloat162(l0,l1);
                *(__nv_bfloat162*)&TL[base+j*4+2]=__nv_bfloat162(l2,l3);
            }
            ((z==0)?g_qns:g_kns)[bh*1024+s]=scale*scale*ss;
        }
    });
}

__global__ __launch_bounds__(256,2) void out_hmma(float* __restrict__ Cout)
{
    extern __shared__ char smc[];
    const int m0=blockIdx.y*128, n0=blockIdx.x*128;
    const int tid=threadIdx.x;
    hmma_gemm_128(smc,g_ath,g_atl,g_woh,g_wol,m0,n0,[&](float* Cs){
        const int half=tid>>7, row=tid&127;
        const float* rp=&Cs[row*132+half*64];
        float* dst=&Cout[(size_t)(m0+row)*1024+n0+half*64];
        #pragma unroll
        for(int j=0;j<16;++j) *(float4*)&dst[j*4]=*(const float4*)&rp[j*4];
    });
}

// ---------- Attention via HMMA, cp.async double-buffered K/V ----------
#define LQ 72
#define SST 72
#define QH_B 0
#define QL_B 18432
#define KV_B 36864
#define KVS  36864           // per-buffer: KH 0, KL 9216, VH 18432, VL 27648
#define S_B  110592
#define PH_B 147456
#define PL_B 165888
#define PC_B 184320
#define LR_B 184832
#define KN_B 185344          // 2 x 64 floats
#define IOY_B 185856         // 2 x 64 floats
#define ATSMB 186368

__global__ __launch_bounds__(256) void attn_hmma(const float* __restrict__ lp,
                                                 const float* __restrict__ bp)
{
    extern __shared__ char smc[];
    const uint32_t smb=smem_u32(smc);
    float* Sf =(float*)(smc+S_B);
    float* PCf=(float*)(smc+PC_B);
    float* LRf=(float*)(smc+LR_B);
    float* KNf=(float*)(smc+KN_B);
    float* IOYf=(float*)(smc+IOY_B);
    const int tid=threadIdx.x, lane=tid&31, wid=tid>>5;
    const int bh=blockIdx.y, q0=blockIdx.x*128;
    const float c_=sp(*lp), sc=sqrtf(c_), bis=sp(*bp)/sc, tc=2.f*c_;

    // stage Q (rows q, cols d) bf16 hi/lo
    {
        const __nv_bfloat16* Qh=&g_qh16[((size_t)bh*1024+q0)*64];
        const __nv_bfloat16* Ql=&g_ql16[((size_t)bh*1024+q0)*64];
        #pragma unroll
        for(int it=0;it<8;++it){
            int idx=tid+it*256, r=idx>>4, q=idx&15;
            *(uint2*)(smc+QH_B+(r*LQ+q*4)*2)=*(const uint2*)&Qh[r*64+q*4];
            *(uint2*)(smc+QL_B+(r*LQ+q*4)*2)=*(const uint2*)&Ql[r*64+q*4];
        }
    }
    const __nv_bfloat16* Kh=&g_kh16[(size_t)bh*1024*64];
    const __nv_bfloat16* Kl=&g_kl16[(size_t)bh*1024*64];
    const __nv_bfloat16* Vh=&g_vth[(size_t)bh*64*1024];
    const __nv_bfloat16* Vl=&g_vtl[(size_t)bh*64*1024];

    // prologue: issue K/V tile 0  (full 128-byte rows: 512 chunks per array)
    {
        char* bb=smc+KV_B;
        #pragma unroll
        for(int it=0;it<8;++it){
            int idx=tid+it*256, arr=idx>>9, ch=idx&511, r=ch>>3, q=ch&7;
            uint32_t sa=smem_u32(bb+arr*9216+(r*LQ+q*8)*2);
            const __nv_bfloat16* gp=
                (arr==0)? Kh+(size_t)r*64+q*8 :
                (arr==1)? Kl+(size_t)r*64+q*8 :
                (arr==2)? Vh+(size_t)r*1024+q*8 : Vl+(size_t)r*1024+q*8;
            cpa16(sa,gp);
        }
        cpcommit();
    }
    const int srow=tid>>1, shalf=tid&1;
    float qn=g_qns[bh*1024+q0+srow];
    float iox=__fdividef(1.f,1.f-c_*qn);
    float knreg=(tid<64)? g_kns[bh*1024+tid] : 0.f;
    float mold=-INFINITY, lhalf=0.f;
    float oacc[8][4]={};
    const int lr=lane&15, lc=lane>>4, l8=lane&7, lk=(lane>>3)&1;
    const int g=lane>>2, tg=lane&3;

    for(int kt=0;kt<16;++kt){
        const int cb=kt&1;
        if(kt<15){
            const int k1=(kt+1)*64;
            char* bb=smc+KV_B+((kt+1)&1)*KVS;
            #pragma unroll
            for(int it=0;it<8;++it){
                int idx=tid+it*256, arr=idx>>9, ch=idx&511, r=ch>>3, q=ch&7;
                uint32_t sa=smem_u32(bb+arr*9216+(r*LQ+q*8)*2);
                const __nv_bfloat16* gp=
                    (arr==0)? Kh+(size_t)(k1+r)*64+q*8 :
                    (arr==1)? Kl+(size_t)(k1+r)*64+q*8 :
                    (arr==2)? Vh+(size_t)r*1024+k1+q*8 : Vl+(size_t)r*1024+k1+q*8;
                cpa16(sa,gp);
            }
            cpcommit();
        }
        if(tid<64){
            KNf[cb*64+tid]=knreg;
            IOYf[cb*64+tid]=__fdividef(1.f,1.f-c_*knreg);
            if(kt<15) knreg=g_kns[bh*1024+(kt+1)*64+tid];
        }
        if(kt<15){ cpwait<1>(); } else { cpwait<0>(); }
        __syncthreads();
        const uint32_t kvb=smb+KV_B+cb*KVS;
        // S = Q K^T
        {
            float sacc[8][4]={};
            #pragma unroll
            for(int ks=0;ks<4;++ks){
                uint32_t ah[4],al[4];
                uint32_t aa=smb+QH_B+((16*wid+lr)*LQ+ks*16+lc*8)*2;
                ldm4(ah[0],ah[1],ah[2],ah[3],aa);
                ldm4(al[0],al[1],al[2],al[3],aa+(QL_B-QH_B));
                #pragma unroll
                for(int nt=0;nt<8;++nt){
                    uint32_t ba=kvb+((nt*8+l8)*LQ+ks*16+lk*8)*2;
                    uint32_t kh0,kh1,kl0,kl1;
                    ldm2(kh0,kh1,ba);
                    ldm2(kl0,kl1,ba+9216);
                    mmabf(sacc[nt],ah,kh0,kh1);
                    mmabf(sacc[nt],al,kh0,kh1);
                    mmabf(sacc[nt],ah,kl0,kl1);
                }
            }
            #pragma unroll
            for(int nt=0;nt<8;++nt){
                *(float2*)&Sf[(16*wid+g)*SST+nt*8+2*tg]  =make_float2(sacc[nt][0],sacc[nt][1]);
                *(float2*)&Sf[(16*wid+8+g)*SST+nt*8+2*tg]=make_float2(sacc[nt][2],sacc[nt][3]);
            }
        }
        __syncthreads();
        // score + online softmax (2 threads per q-row)
        {
            float sv[32];
            const float* sp_=&Sf[srow*SST+shalf*32];
            #pragma unroll
            for(int j=0;j<8;++j){
                float4 s4=*(const float4*)&sp_[j*4];
                float v[4]={s4.x,s4.y,s4.z,s4.w};
                #pragma unroll
                for(int u=0;u<4;++u){
                    int t=shalf*32+j*4+u;
                    float dsq=fmaf(-2.f,v[u],qn+KNf[cb*64+t]);
                    float tt=fminf(iox*IOYf[cb*64+t],1.0e5f);
                    float a0=fmaxf(fmaf(tc*dsq,tt,1.f),1.f+EPSF);
                    sv[j*4+u]=-bis*lg2ap(a0+sqap(fmaf(a0,a0,-1.f)));
                }
            }
            float tm=-INFINITY;
            #pragma unroll
            for(int j=0;j<32;++j) tm=fmaxf(tm,sv[j]);
            tm=fmaxf(tm,__shfl_xor_sync(~0u,tm,1));
            float mn=fmaxf(mold,tm);
            float pc=ex2ap(mold-mn);
            mold=mn;
            float ls=0.f;
            #pragma unroll
            for(int j=0;j<32;++j){ float p=ex2ap(sv[j]-mn); sv[j]=p; ls+=p; }
            lhalf=lhalf*pc+ls;
            if(shalf==0) PCf[srow]=pc;
            #pragma unroll
            for(int j=0;j<16;++j){
                __nv_bfloat16 h0,l0,h1,l1;
                bfsplit(sv[2*j],h0,l0); bfsplit(sv[2*j+1],h1,l1);
                int col=shalf*32+2*j;
                *(__nv_bfloat162*)(smc+PH_B+(srow*LQ+col)*2)=__nv_bfloat162(h0,h1);
                *(__nv_bfloat162*)(smc+PL_B+(srow*LQ+col)*2)=__nv_bfloat162(l0,l1);
            }
        }
        __syncthreads();
        // O = O*pc + P V
        {
            float pc0=PCf[16*wid+g], pc8=PCf[16*wid+8+g];
            #pragma unroll
            for(int nt=0;nt<8;++nt){
                oacc[nt][0]*=pc0; oacc[nt][1]*=pc0;
                oacc[nt][2]*=pc8; oacc[nt][3]*=pc8;
            }
            #pragma unroll
            for(int ks=0;ks<4;++ks){
                uint32_t ph[4],pl[4];
                uint32_t pa=smb+PH_B+((16*wid+lr)*LQ+ks*16+lc*8)*2;
                ldm4(ph[0],ph[1],ph[2],ph[3],pa);
                ldm4(pl[0],pl[1],pl[2],pl[3],pa+(PL_B-PH_B));
                #pragma unroll
                for(int nt=0;nt<8;++nt){
                    uint32_t va=kvb+18432+((nt*8+l8)*LQ+ks*16+lk*8)*2;
                    uint32_t vh0,vh1,vl0,vl1;
                    ldm2(vh0,vh1,va);
                    ldm2(vl0,vl1,va+9216);
                    mmabf(oacc[nt],ph,vh0,vh1);
                    mmabf(oacc[nt],pl,vh0,vh1);
                    mmabf(oacc[nt],ph,vl0,vl1);
                }
            }
        }
        __syncthreads();
    }
    {
        float lf=lhalf+__shfl_xor_sync(~0u,lhalf,1);
        if(shalf==0) LRf[srow]=__fdividef(1.f,lf);
    }
    __syncthreads();
    {
        float i0=LRf[16*wid+g], i8=LRf[16*wid+8+g];
        float ss0=0.f, ss8=0.f;
        #pragma unroll
        for(int nt=0;nt<8;++nt){
            float e0=oacc[nt][0]*i0, e1=oacc[nt][1]*i0;
            float e2=oacc[nt][2]*i8, e3=oacc[nt][3]*i8;
            ss0=fmaf(e0,e0,fmaf(e1,e1,ss0));
            ss8=fmaf(e2,e2,fmaf(e3,e3,ss8));
        }
        ss0+=__shfl_xor_sync(~0u,ss0,1); ss0+=__shfl_xor_sync(~0u,ss0,2);
        ss8+=__shfl_xor_sync(~0u,ss8,1); ss8+=__shfl_xor_sync(~0u,ss8,2);
        const float th=1.f-sc*EPSF;
        float n0=fmaxf(sqrtf(ss0),EPSF), scn0=sc*n0, t10=tanhf(scn0);
        float sc0=(t10<th)?i0:(atanhf(th)/scn0)*i0;
        float n8=fmaxf(sqrtf(ss8),EPSF), scn8=sc*n8, t18=tanhf(scn8);
        float sc8=(t18<th)?i8:(atanhf(th)/scn8)*i8;
        const int b=bh>>4, hh=bh&15;
        const int s0g=q0+16*wid+g, s8g=s0g+8;
        #pragma unroll
        for(int nt=0;nt<8;++nt){
            int col=hh*64+nt*8+2*tg;
            __nv_bfloat16 h0,l0,h1,l1;
            bfsplit(oacc[nt][0]*sc0,h0,l0); bfsplit(oacc[nt][1]*sc0,h1,l1);
            *(__nv_bfloat162*)&g_ath[((size_t)(b*1024+s0g))*1024+col]=__nv_bfloat162(h0,h1);
            *(__nv_bfloat162*)&g_atl[((size_t)(b*1024+s0g))*1024+col]=__nv_bfloat162(l0,l1);
            bfsplit(oacc[nt][2]*sc8,h0,l0); bfsplit(oacc[nt][3]*sc8,h1,l1);
            *(__nv_bfloat162*)&g_ath[((size_t)(b*1024+s8g))*1024+col]=__nv_bfloat162(h0,h1);
            *(__nv_bfloat162*)&g_atl[((size_t)(b*1024+s8g))*1024+col]=__nv_bfloat162(l0,l1);
        }
    }
}

extern "C" void kernel_launch(void* const* d_in, const int* in_sizes, int n_in,
                              void* d_out, int out_size)
{
    (void)in_sizes;(void)n_in;(void)out_size;
    const float* x   =(const float*)d_in[0];
    const float* Wq  =(const float*)d_in[1];
    const float* Wk  =(const float*)d_in[2];
    const float* Wv  =(const float*)d_in[3];
    const float* Wo  =(const float*)d_in[4];
    const float* logc=(const float*)d_in[5];
    const float* beta=(const float*)d_in[6];
    float* out=(float*)d_out;

    cudaFuncSetAttribute(qkv_hmma, cudaFuncAttributeMaxDynamicSharedMemorySize, QSMB);
    cudaFuncSetAttribute(attn_hmma, cudaFuncAttributeMaxDynamicSharedMemorySize, ATSMB);
    cudaFuncSetAttribute(out_hmma, cudaFuncAttributeMaxDynamicSharedMemorySize, QSMB);

    split_k<<<2048,256>>>(x,Wq,Wk,Wv,Wo);
    qkv_hmma<<<dim3(8,16,3),256,QSMB>>>(logc);
    attn_hmma<<<dim3(8,32),256,ATSMB>>>(logc,beta);
    out_hmma<<<dim3(8,16),256,QSMB>>>(out);
}

// round 16
// speedup vs baseline: 4.4997x; 1.0374x over previous
#include <cuda_runtime.h>
#include <cuda_bf16.h>
#include <math.h>
#include <stdint.h>

#define S_ 1024
#define D_ 1024
#define H_ 16
#define EPSF 1e-5f
typedef unsigned long long ull;

__device__ float g_qns[2*H_*S_];
__device__ float g_kns[2*H_*S_];
__device__ __align__(16) __nv_bfloat16 g_xh[2048*1024];
__device__ __align__(16) __nv_bfloat16 g_xl[2048*1024];
__device__ __align__(16) __nv_bfloat16 g_wh[3*1024*1024];
__device__ __align__(16) __nv_bfloat16 g_wl[3*1024*1024];
__device__ __align__(16) __nv_bfloat16 g_woh[1024*1024];
__device__ __align__(16) __nv_bfloat16 g_wol[1024*1024];
__device__ __align__(16) __nv_bfloat16 g_qh16[2*H_*1024*64];
__device__ __align__(16) __nv_bfloat16 g_ql16[2*H_*1024*64];
__device__ __align__(16) __nv_bfloat16 g_kh16[2*H_*1024*64];
__device__ __align__(16) __nv_bfloat16 g_kl16[2*H_*1024*64];
__device__ __align__(16) __nv_bfloat16 g_vth[2*H_*64*1024];   // [bh][d][s]
__device__ __align__(16) __nv_bfloat16 g_vtl[2*H_*64*1024];
__device__ __align__(16) __nv_bfloat16 g_ath[2048*1024];
__device__ __align__(16) __nv_bfloat16 g_atl[2048*1024];

__device__ __forceinline__ float sqap(float x){float r;asm("sqrt.approx.f32 %0,%1;":"=f"(r):"f"(x));return r;}
__device__ __forceinline__ float lg2ap(float x){float r;asm("lg2.approx.f32 %0,%1;":"=f"(r):"f"(x));return r;}
__device__ __forceinline__ float ex2ap(float x){float r;asm("ex2.approx.f32 %0,%1;":"=f"(r):"f"(x));return r;}
__device__ __forceinline__ float sp(float x){return log1pf(expf(x));}
__device__ __forceinline__ uint32_t smem_u32(const void* p){
    uint32_t a; asm("{ .reg .u64 t; cvta.to.shared.u64 t, %1; cvt.u32.u64 %0, t; }":"=r"(a):"l"(p)); return a;
}
__device__ __forceinline__ void ldm4(uint32_t&a0,uint32_t&a1,uint32_t&a2,uint32_t&a3,uint32_t ad){
    asm volatile("ldmatrix.sync.aligned.m8n8.x4.shared.b16 {%0,%1,%2,%3}, [%4];"
        :"=r"(a0),"=r"(a1),"=r"(a2),"=r"(a3):"r"(ad));
}
__device__ __forceinline__ void ldm2(uint32_t&b0,uint32_t&b1,uint32_t ad){
    asm volatile("ldmatrix.sync.aligned.m8n8.x2.shared.b16 {%0,%1}, [%2];"
        :"=r"(b0),"=r"(b1):"r"(ad));
}
__device__ __forceinline__ void mmabf(float* c,const uint32_t* a,uint32_t b0,uint32_t b1){
    asm volatile("mma.sync.aligned.m16n8k16.row.col.f32.bf16.bf16.f32 "
        "{%0,%1,%2,%3},{%4,%5,%6,%7},{%8,%9},{%0,%1,%2,%3};"
        :"+f"(c[0]),"+f"(c[1]),"+f"(c[2]),"+f"(c[3])
        :"r"(a[0]),"r"(a[1]),"r"(a[2]),"r"(a[3]),"r"(b0),"r"(b1));
}
__device__ __forceinline__ void bfsplit(float v,__nv_bfloat16&h,__nv_bfloat16&l){
    h=__float2bfloat16(v); l=__float2bfloat16(v-__bfloat162float(h));
}
__device__ __forceinline__ void cpa16(uint32_t sa,const void* g){
    asm volatile("cp.async.cg.shared.global [%0], [%1], 16;"::"r"(sa),"l"(g):"memory");
}
__device__ __forceinline__ void cpcommit(){ asm volatile("cp.async.commit_group;":::"memory"); }
template<int N> __device__ __forceinline__ void cpwait(){ asm volatile("cp.async.wait_group %0;"::"n"(N):"memory"); }

// ---------- split fp32 -> bf16 hi/lo ----------
__global__ void split_k(const float* __restrict__ X,const float* __restrict__ Wq,
                        const float* __restrict__ Wk,const float* __restrict__ Wv,
                        const float* __restrict__ Wo)
{
    const int total=2097152+4194304;
    for(int i=blockIdx.x*blockDim.x+threadIdx.x;i<total;i+=gridDim.x*blockDim.x){
        float v; __nv_bfloat16 *ph,*pl;
        if(i<2097152){ v=X[i]; ph=&g_xh[i]; pl=&g_xl[i]; }
        else{
            int j=i-2097152;
            if(j<3145728){ int z=j>>20, off=j&1048575;
                v=(z==0?Wq:(z==1?Wk:Wv))[off]; ph=&g_wh[j]; pl=&g_wl[j]; }
            else{ int off=j-3145728; v=Wo[off]; ph=&g_woh[off]; pl=&g_wol[off]; }
        }
        bfsplit(v,*ph,*pl);
    }
}

// ---------- 64x128 GEMM tile via HMMA bf16 split, cp.async double-buffer ----------
#define LDA 40
#define ARR_A 5120            // 64*40*2
#define ARR_Bw 10240          // 128*40*2
#define TILE64 30720          // AH|AL|BH|BL per buffer
#define QSMB   61440

template<typename EPI>
__device__ __forceinline__ void hmma_gemm_64x128(
    char* smc,const __nv_bfloat16* AH,const __nv_bfloat16* AL,
    const __nv_bfloat16* BH,const __nv_bfloat16* BL,
    int m0,int n0,EPI epi)
{
    float* Cs=(float*)smc;
    const uint32_t smb=smem_u32(smc);
    const int tid=threadIdx.x, lane=tid&31, wid=tid>>5;
    const int wm=wid>>2, wn=wid&3;
    float acc[2][4][4]={};
    const int lr=lane&15, lc=lane>>4;
    const int l8=lane&7, lk=(lane>>3)&1;

    // staging: 1536 chunks of 16B (A: 512, B: 1024)
    auto stage=[&](char* bb,int k0){
        #pragma unroll
        for(int it=0;it<6;++it){
            int idx=tid+it*256;
            if(idx<512){
                int arr=idx>>8, ch=idx&255, r=ch>>2, q=ch&3;
                cpa16(smem_u32(bb+arr*ARR_A+(r*LDA+q*8)*2),
                      (arr?AL:AH)+(size_t)(m0+r)*1024+k0+q*8);
            }else{
                int j=idx-512, arr=j>>9, ch=j&511, r=ch>>2, q=ch&3;
                cpa16(smem_u32(bb+2*ARR_A+arr*ARR_Bw+(r*LDA+q*8)*2),
                      (arr?BL:BH)+(size_t)(n0+r)*1024+k0+q*8);
            }
        }
        cpcommit();
    };
    stage(smc,0);
    for(int kt=0;kt<32;++kt){
        if(kt<31){ stage(smc+((kt+1)&1)*TILE64,(kt+1)*32); cpwait<1>(); }
        else cpwait<0>();
        __syncthreads();
        const uint32_t bb=smb+(kt&1)*TILE64;
        #pragma unroll
        for(int ks=0;ks<2;++ks){
            uint32_t ah[2][4], al[2][4];
            #pragma unroll
            for(int mt=0;mt<2;++mt){
                uint32_t aa=bb+((wm*32+mt*16+lr)*LDA+ks*16+lc*8)*2;
                ldm4(ah[mt][0],ah[mt][1],ah[mt][2],ah[mt][3],aa);
                ldm4(al[mt][0],al[mt][1],al[mt][2],al[mt][3],aa+ARR_A);
            }
            #pragma unroll
            for(int nt=0;nt<4;++nt){
                uint32_t ba=bb+2*ARR_A+((wn*32+nt*8+l8)*LDA+ks*16+lk*8)*2;
                uint32_t bh0,bh1,bl0,bl1;
                ldm2(bh0,bh1,ba);
                ldm2(bl0,bl1,ba+ARR_Bw);
                #pragma unroll
                for(int mt=0;mt<2;++mt){
                    mmabf(acc[mt][nt],ah[mt],bh0,bh1);
                    mmabf(acc[mt][nt],al[mt],bh0,bh1);
                    mmabf(acc[mt][nt],ah[mt],bl0,bl1);
                }
            }
        }
        __syncthreads();
    }
    {
        int g=lane>>2, tg=lane&3;
        #pragma unroll
        for(int mt=0;mt<2;++mt){
            int r0=wm*32+mt*16+g;
            #pragma unroll
            for(int nt=0;nt<4;++nt){
                int col=wn*32+nt*8+2*tg;
                *(float2*)&Cs[r0*132+col]    =make_float2(acc[mt][nt][0],acc[mt][nt][1]);
                *(float2*)&Cs[(r0+8)*132+col]=make_float2(acc[mt][nt][2],acc[mt][nt][3]);
            }
        }
    }
    __syncthreads();
    epi(Cs);
}

__global__ __launch_bounds__(256,3) void qkv_hmma(const float* __restrict__ logc)
{
    extern __shared__ char smc[];
    const int z=blockIdx.z, m0=blockIdx.y*64, n0=blockIdx.x*128;
    const __nv_bfloat16* WH=g_wh+((size_t)z<<20);
    const __nv_bfloat16* WL=g_wl+((size_t)z<<20);
    const float c_=sp(*logc), sc=sqrtf(c_);
    const int tid=threadIdx.x;
    hmma_gemm_64x128(smc,g_xh,g_xl,WH,WL,m0,n0,[&](float* Cs){
        if(tid>=128) return;
        const int half=tid>>6, row=tid&63;
        const float* rp=&Cs[row*132+half*64];
        float ss=0.f;
        #pragma unroll
        for(int j=0;j<16;++j){
            float4 v=*(const float4*)&rp[j*4];
            ss=fmaf(v.x,v.x,fmaf(v.y,v.y,fmaf(v.z,v.z,fmaf(v.w,v.w,ss))));
        }
        const int m=m0+row, b=m>>10, s=m&1023;
        const int hh=blockIdx.x*2+half, bh=b*H_+hh;
        float n=fmaxf(sqrtf(ss),EPSF), scn=sc*n, t1=tanhf(scn);
        float scale;
        if(z<2) scale=t1/scn;
        else { float th=1.f-sc*EPSF; scale=(t1<th)?1.f:(atanhf(th)/scn); }
        if(z==2){
            #pragma unroll
            for(int j=0;j<64;++j){
                __nv_bfloat16 h,l; bfsplit(rp[j]*scale,h,l);
                g_vth[((size_t)bh*64+j)*1024+s]=h;
                g_vtl[((size_t)bh*64+j)*1024+s]=l;
            }
        }else{
            __nv_bfloat16* TH=(z==0)?g_qh16:g_kh16;
            __nv_bfloat16* TL=(z==0)?g_ql16:g_kl16;
            size_t base=((size_t)bh*1024+s)*64;
            #pragma unroll
            for(int j=0;j<16;++j){
                float4 v=*(const float4*)&rp[j*4];
                __nv_bfloat16 h0,l0,h1,l1,h2,l2,h3,l3;
                bfsplit(v.x*scale,h0,l0); bfsplit(v.y*scale,h1,l1);
                bfsplit(v.z*scale,h2,l2); bfsplit(v.w*scale,h3,l3);
                *(__nv_bfloat162*)&TH[base+j*4]  =__nv_bfloat162(h0,h1);
                *(__nv_bfloat162*)&TH[base+j*4+2]=__nv_bfloat162(h2,h3);
                *(__nv_bfloat162*)&TL[base+j*4]  =__nv_bfloat162(l0,l1);
                *(__nv_bfloat162*)&TL[base+j*4+2]=__nv_bfloat162(l2,l3);
            }
            ((z==0)?g_qns:g_kns)[bh*1024+s]=scale*scale*ss;
        }
    });
}

__global__ __launch_bounds__(256,3) void out_hmma(float* __restrict__ Cout)
{
    extern __shared__ char smc[];
    const int m0=blockIdx.y*64, n0=blockIdx.x*128;
    const int tid=threadIdx.x;
    hmma_gemm_64x128(smc,g_ath,g_atl,g_woh,g_wol,m0,n0,[&](float* Cs){
        if(tid>=128) return;
        const int half=tid>>6, row=tid&63;
        const float* rp=&Cs[row*132+half*64];
        float* dst=&Cout[(size_t)(m0+row)*1024+n0+half*64];
        #pragma unroll
        for(int j=0;j<16;++j) *(float4*)&dst[j*4]=*(const float4*)&rp[j*4];
    });
}

// ---------- Attention via HMMA: single-buffer KV, P unioned over S ----------
#define LQ 72
#define SST 72
#define QH_B 0
#define QL_B 18432
#define KV_B 36864           // KH 0, KL 9216, VH 18432, VL 27648
#define S_B  73728           // 36864 bytes (128 x 72 floats)
#define PH_B 73728           // union with S (write after all S reads)
#define PL_B 92160
#define PC_B 110592
#define LR_B 111104
#define KN_B 111616
#define IOY_B 111872
#define ATSMB 112128

__global__ __launch_bounds__(256) void attn_hmma(const float* __restrict__ lp,
                                                 const float* __restrict__ bp)
{
    extern __shared__ char smc[];
    const uint32_t smb=smem_u32(smc);
    float* Sf =(float*)(smc+S_B);
    float* PCf=(float*)(smc+PC_B);
    float* LRf=(float*)(smc+LR_B);
    float* KNf=(float*)(smc+KN_B);
    float* IOYf=(float*)(smc+IOY_B);
    const int tid=threadIdx.x, lane=tid&31, wid=tid>>5;
    const int bh=blockIdx.y, q0=blockIdx.x*128;
    const float c_=sp(*lp), sc=sqrtf(c_), bis=sp(*bp)/sc, tc=2.f*c_;

    // stage Q (rows q, cols d) bf16 hi/lo
    {
        const __nv_bfloat16* Qh=&g_qh16[((size_t)bh*1024+q0)*64];
        const __nv_bfloat16* Ql=&g_ql16[((size_t)bh*1024+q0)*64];
        #pragma unroll
        for(int it=0;it<8;++it){
            int idx=tid+it*256, r=idx>>4, q=idx&15;
            *(uint2*)(smc+QH_B+(r*LQ+q*4)*2)=*(const uint2*)&Qh[r*64+q*4];
            *(uint2*)(smc+QL_B+(r*LQ+q*4)*2)=*(const uint2*)&Ql[r*64+q*4];
        }
    }
    const __nv_bfloat16* Kh=&g_kh16[(size_t)bh*1024*64];
    const __nv_bfloat16* Kl=&g_kl16[(size_t)bh*1024*64];
    const __nv_bfloat16* Vh=&g_vth[(size_t)bh*64*1024];
    const __nv_bfloat16* Vl=&g_vtl[(size_t)bh*64*1024];

    auto stage_kv=[&](int k0){
        char* bb=smc+KV_B;
        #pragma unroll
        for(int it=0;it<8;++it){
            int idx=tid+it*256, arr=idx>>9, ch=idx&511, r=ch>>3, q=ch&7;
            uint32_t sa=smem_u32(bb+arr*9216+(r*LQ+q*8)*2);
            const __nv_bfloat16* gp=
                (arr==0)? Kh+(size_t)(k0+r)*64+q*8 :
                (arr==1)? Kl+(size_t)(k0+r)*64+q*8 :
                (arr==2)? Vh+(size_t)r*1024+k0+q*8 : Vl+(size_t)r*1024+k0+q*8;
            cpa16(sa,gp);
        }
        cpcommit();
    };
    stage_kv(0);

    const int srow=tid>>1, shalf=tid&1;
    float qn=g_qns[bh*1024+q0+srow];
    float iox=__fdividef(1.f,1.f-c_*qn);
    float knreg=(tid<64)? g_kns[bh*1024+tid] : 0.f;
    float mold=-INFINITY, lhalf=0.f;
    float oacc[8][4]={};
    const int lr=lane&15, lc=lane>>4, l8=lane&7, lk=(lane>>3)&1;
    const int g=lane>>2, tg=lane&3;

    for(int kt=0;kt<16;++kt){
        if(tid<64){
            KNf[tid]=knreg;
            IOYf[tid]=__fdividef(1.f,1.f-c_*knreg);
            if(kt<15) knreg=g_kns[bh*1024+(kt+1)*64+tid];
        }
        cpwait<0>();
        __syncthreads();
        const uint32_t kvb=smb+KV_B;
        // S = Q K^T
        {
            float sacc[8][4]={};
            #pragma unroll
            for(int ks=0;ks<4;++ks){
                uint32_t ah[4],al[4];
                uint32_t aa=smb+QH_B+((16*wid+lr)*LQ+ks*16+lc*8)*2;
                ldm4(ah[0],ah[1],ah[2],ah[3],aa);
                ldm4(al[0],al[1],al[2],al[3],aa+(QL_B-QH_B));
                #pragma unroll
                for(int nt=0;nt<8;++nt){
                    uint32_t ba=kvb+((nt*8+l8)*LQ+ks*16+lk*8)*2;
                    uint32_t kh0,kh1,kl0,kl1;
                    ldm2(kh0,kh1,ba);
                    ldm2(kl0,kl1,ba+9216);
                    mmabf(sacc[nt],ah,kh0,kh1);
                    mmabf(sacc[nt],al,kh0,kh1);
                    mmabf(sacc[nt],ah,kl0,kl1);
                }
            }
            #pragma unroll
            for(int nt=0;nt<8;++nt){
                *(float2*)&Sf[(16*wid+g)*SST+nt*8+2*tg]  =make_float2(sacc[nt][0],sacc[nt][1]);
                *(float2*)&Sf[(16*wid+8+g)*SST+nt*8+2*tg]=make_float2(sacc[nt][2],sacc[nt][3]);
            }
        }
        __syncthreads();
        // score (reads S) ... sync ... softmax + P write (P unioned over S)
        {
            float sv[32];
            const float* sp_=&Sf[srow*SST+shalf*32];
            #pragma unroll
            for(int j=0;j<8;++j){
                float4 s4=*(const float4*)&sp_[j*4];
                float v[4]={s4.x,s4.y,s4.z,s4.w};
                #pragma unroll
                for(int u=0;u<4;++u){
                    int t=shalf*32+j*4+u;
                    float dsq=fmaf(-2.f,v[u],qn+KNf[t]);
                    float tt=fminf(iox*IOYf[t],1.0e5f);
                    float a0=fmaxf(fmaf(tc*dsq,tt,1.f),1.f+EPSF);
                    sv[j*4+u]=-bis*lg2ap(a0+sqap(fmaf(a0,a0,-1.f)));
                }
            }
            __syncthreads();   // all S reads done before P overwrites S region
            float tm=-INFINITY;
            #pragma unroll
            for(int j=0;j<32;++j) tm=fmaxf(tm,sv[j]);
            tm=fmaxf(tm,__shfl_xor_sync(~0u,tm,1));
            float mn=fmaxf(mold,tm);
            float pc=ex2ap(mold-mn);
            mold=mn;
            float ls=0.f;
            #pragma unroll
            for(int j=0;j<32;++j){ float p=ex2ap(sv[j]-mn); sv[j]=p; ls+=p; }
            lhalf=lhalf*pc+ls;
            if(shalf==0) PCf[srow]=pc;
            #pragma unroll
            for(int j=0;j<16;++j){
                __nv_bfloat16 h0,l0,h1,l1;
                bfsplit(sv[2*j],h0,l0); bfsplit(sv[2*j+1],h1,l1);
                int col=shalf*32+2*j;
                *(__nv_bfloat162*)(smc+PH_B+(srow*LQ+col)*2)=__nv_bfloat162(h0,h1);
                *(__nv_bfloat162*)(smc+PL_B+(srow*LQ+col)*2)=__nv_bfloat162(l0,l1);
            }
        }
        __syncthreads();
        // O = O*pc + P V
        {
            float pc0=PCf[16*wid+g], pc8=PCf[16*wid+8+g];
            #pragma unroll
            for(int nt=0;nt<8;++nt){
                oacc[nt][0]*=pc0; oacc[nt][1]*=pc0;
                oacc[nt][2]*=pc8; oacc[nt][3]*=pc8;
            }
            #pragma unroll
            for(int ks=0;ks<4;++ks){
                uint32_t ph[4],pl[4];
                uint32_t pa=smb+PH_B+((16*wid+lr)*LQ+ks*16+lc*8)*2;
                ldm4(ph[0],ph[1],ph[2],ph[3],pa);
                ldm4(pl[0],pl[1],pl[2],pl[3],pa+(PL_B-PH_B));
                #pragma unroll
                for(int nt=0;nt<8;++nt){
                    uint32_t va=kvb+18432+((nt*8+l8)*LQ+ks*16+lk*8)*2;
                    uint32_t vh0,vh1,vl0,vl1;
                    ldm2(vh0,vh1,va);
                    ldm2(vl0,vl1,va+9216);
                    mmabf(oacc[nt],ph,vh0,vh1);
                    mmabf(oacc[nt],pl,vh0,vh1);
                    mmabf(oacc[nt],ph,vl0,vl1);
                }
            }
        }
        __syncthreads();   // all P / KV reads done
        if(kt<15) stage_kv((kt+1)*64);
    }
    {
        float lf=lhalf+__shfl_xor_sync(~0u,lhalf,1);
        if(shalf==0) LRf[srow]=__fdividef(1.f,lf);
    }
    __syncthreads();
    {
        float i0=LRf[16*wid+g], i8=LRf[16*wid+8+g];
        float ss0=0.f, ss8=0.f;
        #pragma unroll
        for(int nt=0;nt<8;++nt){
            float e0=oacc[nt][0]*i0, e1=oacc[nt][1]*i0;
            float e2=oacc[nt][2]*i8, e3=oacc[nt][3]*i8;
            ss0=fmaf(e0,e0,fmaf(e1,e1,ss0));
            ss8=fmaf(e2,e2,fmaf(e3,e3,ss8));
        }
        ss0+=__shfl_xor_sync(~0u,ss0,1); ss0+=__shfl_xor_sync(~0u,ss0,2);
        ss8+=__shfl_xor_sync(~0u,ss8,1); ss8+=__shfl_xor_sync(~0u,ss8,2);
        const float th=1.f-sc*EPSF;
        float n0=fmaxf(sqrtf(ss0),EPSF), scn0=sc*n0, t10=tanhf(scn0);
        float sc0=(t10<th)?i0:(atanhf(th)/scn0)*i0;
        float n8=fmaxf(sqrtf(ss8),EPSF), scn8=sc*n8, t18=tanhf(scn8);
        float sc8=(t18<th)?i8:(atanhf(th)/scn8)*i8;
        const int b=bh>>4, hh=bh&15;
        const int s0g=q0+16*wid+g, s8g=s0g+8;
        #pragma unroll
        for(int nt=0;nt<8;++nt){
            int col=hh*64+nt*8+2*tg;
            __nv_bfloat16 h0,l0,h1,l1;
            bfsplit(oacc[nt][0]*sc0,h0,l0); bfsplit(oacc[nt][1]*sc0,h1,l1);
            *(__nv_bfloat162*)&g_ath[((size_t)(b*1024+s0g))*1024+col]=__nv_bfloat162(h0,h1);
            *(__nv_bfloat162*)&g_atl[((size_t)(b*1024+s0g))*1024+col]=__nv_bfloat162(l0,l1);
            bfsplit(oacc[nt][2]*sc8,h0,l0); bfsplit(oacc[nt][3]*sc8,h1,l1);
            *(__nv_bfloat162*)&g_ath[((size_t)(b*1024+s8g))*1024+col]=__nv_bfloat162(h0,h1);
            *(__nv_bfloat162*)&g_atl[((size_t)(b*1024+s8g))*1024+col]=__nv_bfloat162(l0,l1);
        }
    }
}

extern "C" void kernel_launch(void* const* d_in, const int* in_sizes, int n_in,
                              void* d_out, int out_size)
{
    (void)in_sizes;(void)n_in;(void)out_size;
    const float* x   =(const float*)d_in[0];
    const float* Wq  =(const float*)d_in[1];
    const float* Wk  =(const float*)d_in[2];
    const float* Wv  =(const float*)d_in[3];
    const float* Wo  =(const float*)d_in[4];
    const float* logc=(const float*)d_in[5];
    const float* beta=(const float*)d_in[6];
    float* out=(float*)d_out;

    cudaFuncSetAttribute(qkv_hmma, cudaFuncAttributeMaxDynamicSharedMemorySize, QSMB);
    cudaFuncSetAttribute(attn_hmma, cudaFuncAttributeMaxDynamicSharedMemorySize, ATSMB);
    cudaFuncSetAttribute(out_hmma, cudaFuncAttributeMaxDynamicSharedMemorySize, QSMB);

    split_k<<<2048,256>>>(x,Wq,Wk,Wv,Wo);
    qkv_hmma<<<dim3(8,32,3),256,QSMB>>>(logc);
    attn_hmma<<<dim3(8,32),256,ATSMB>>>(logc,beta);
    out_hmma<<<dim3(8,32),256,QSMB>>>(out);
}

// round 17
// speedup vs baseline: 4.5002x; 1.0001x over previous
#include <cuda_runtime.h>
#include <cuda_bf16.h>
#include <math.h>
#include <stdint.h>

#define S_ 1024
#define D_ 1024
#define H_ 16
#define EPSF 1e-5f
typedef unsigned long long ull;

__device__ float g_qns[2*H_*S_];
__device__ float g_kns[2*H_*S_];
__device__ __align__(16) __nv_bfloat16 g_xh[2048*1024];
__device__ __align__(16) __nv_bfloat16 g_xl[2048*1024];
__device__ __align__(16) __nv_bfloat16 g_wh[3*1024*1024];
__device__ __align__(16) __nv_bfloat16 g_wl[3*1024*1024];
__device__ __align__(16) __nv_bfloat16 g_woh[1024*1024];
__device__ __align__(16) __nv_bfloat16 g_wol[1024*1024];
__device__ __align__(16) __nv_bfloat16 g_qh16[2*H_*1024*64];
__device__ __align__(16) __nv_bfloat16 g_ql16[2*H_*1024*64];
__device__ __align__(16) __nv_bfloat16 g_kh16[2*H_*1024*64];
__device__ __align__(16) __nv_bfloat16 g_kl16[2*H_*1024*64];
__device__ __align__(16) __nv_bfloat16 g_vth[2*H_*64*1024];   // [bh][d][s]
__device__ __align__(16) __nv_bfloat16 g_vtl[2*H_*64*1024];
__device__ __align__(16) __nv_bfloat16 g_ath[2048*1024];
__device__ __align__(16) __nv_bfloat16 g_atl[2048*1024];

__device__ __forceinline__ float sqap(float x){float r;asm("sqrt.approx.f32 %0,%1;":"=f"(r):"f"(x));return r;}
__device__ __forceinline__ float lg2ap(float x){float r;asm("lg2.approx.f32 %0,%1;":"=f"(r):"f"(x));return r;}
__device__ __forceinline__ float ex2ap(float x){float r;asm("ex2.approx.f32 %0,%1;":"=f"(r):"f"(x));return r;}
__device__ __forceinline__ float sp(float x){return log1pf(expf(x));}
__device__ __forceinline__ uint32_t smem_u32(const void* p){
    uint32_t a; asm("{ .reg .u64 t; cvta.to.shared.u64 t, %1; cvt.u32.u64 %0, t; }":"=r"(a):"l"(p)); return a;
}
__device__ __forceinline__ void ldm4(uint32_t&a0,uint32_t&a1,uint32_t&a2,uint32_t&a3,uint32_t ad){
    asm volatile("ldmatrix.sync.aligned.m8n8.x4.shared.b16 {%0,%1,%2,%3}, [%4];"
        :"=r"(a0),"=r"(a1),"=r"(a2),"=r"(a3):"r"(ad));
}
__device__ __forceinline__ void ldm2(uint32_t&b0,uint32_t&b1,uint32_t ad){
    asm volatile("ldmatrix.sync.aligned.m8n8.x2.shared.b16 {%0,%1}, [%2];"
        :"=r"(b0),"=r"(b1):"r"(ad));
}
__device__ __forceinline__ void mmabf(float* c,const uint32_t* a,uint32_t b0,uint32_t b1){
    asm volatile("mma.sync.aligned.m16n8k16.row.col.f32.bf16.bf16.f32 "
        "{%0,%1,%2,%3},{%4,%5,%6,%7},{%8,%9},{%0,%1,%2,%3};"
        :"+f"(c[0]),"+f"(c[1]),"+f"(c[2]),"+f"(c[3])
        :"r"(a[0]),"r"(a[1]),"r"(a[2]),"r"(a[3]),"r"(b0),"r"(b1));
}
__device__ __forceinline__ void bfsplit(float v,__nv_bfloat16&h,__nv_bfloat16&l){
    h=__float2bfloat16(v); l=__float2bfloat16(v-__bfloat162float(h));
}
__device__ __forceinline__ void cpa16(uint32_t sa,const void* g){
    asm volatile("cp.async.cg.shared.global [%0], [%1], 16;"::"r"(sa),"l"(g):"memory");
}
__device__ __forceinline__ void cpcommit(){ asm volatile("cp.async.commit_group;":::"memory"); }
template<int N> __device__ __forceinline__ void cpwait(){ asm volatile("cp.async.wait_group %0;"::"n"(N):"memory"); }

// ---------- split fp32 -> bf16 hi/lo ----------
__global__ void split_k(const float* __restrict__ X,const float* __restrict__ Wq,
                        const float* __restrict__ Wk,const float* __restrict__ Wv,
                        const float* __restrict__ Wo)
{
    const int total=2097152+4194304;
    for(int i=blockIdx.x*blockDim.x+threadIdx.x;i<total;i+=gridDim.x*blockDim.x){
        float v; __nv_bfloat16 *ph,*pl;
        if(i<2097152){ v=X[i]; ph=&g_xh[i]; pl=&g_xl[i]; }
        else{
            int j=i-2097152;
            if(j<3145728){ int z=j>>20, off=j&1048575;
                v=(z==0?Wq:(z==1?Wk:Wv))[off]; ph=&g_wh[j]; pl=&g_wl[j]; }
            else{ int off=j-3145728; v=Wo[off]; ph=&g_woh[off]; pl=&g_wol[off]; }
        }
        bfsplit(v,*ph,*pl);
    }
}

// ---------- 64x128 GEMM tile via HMMA bf16 split, cp.async double-buffer ----------
#define LDA 40
#define ARR_A 5120            // 64*40*2
#define ARR_Bw 10240          // 128*40*2
#define TILE64 30720
#define QSMB   61440

template<typename EPI>
__device__ __forceinline__ void hmma_gemm_64x128(
    char* smc,const __nv_bfloat16* AH,const __nv_bfloat16* AL,
    const __nv_bfloat16* BH,const __nv_bfloat16* BL,
    int m0,int n0,EPI epi)
{
    float* Cs=(float*)smc;
    const uint32_t smb=smem_u32(smc);
    const int tid=threadIdx.x, lane=tid&31, wid=tid>>5;
    const int wm=wid>>2, wn=wid&3;
    float acc[2][4][4]={};
    const int lr=lane&15, lc=lane>>4;
    const int l8=lane&7, lk=(lane>>3)&1;

    auto stage=[&](char* bb,int k0){
        #pragma unroll
        for(int it=0;it<6;++it){
            int idx=tid+it*256;
            if(idx<512){
                int arr=idx>>8, ch=idx&255, r=ch>>2, q=ch&3;
                cpa16(smem_u32(bb+arr*ARR_A+(r*LDA+q*8)*2),
                      (arr?AL:AH)+(size_t)(m0+r)*1024+k0+q*8);
            }else{
                int j=idx-512, arr=j>>9, ch=j&511, r=ch>>2, q=ch&3;
                cpa16(smem_u32(bb+2*ARR_A+arr*ARR_Bw+(r*LDA+q*8)*2),
                      (arr?BL:BH)+(size_t)(n0+r)*1024+k0+q*8);
            }
        }
        cpcommit();
    };
    stage(smc,0);
    for(int kt=0;kt<32;++kt){
        if(kt<31){ stage(smc+((kt+1)&1)*TILE64,(kt+1)*32); cpwait<1>(); }
        else cpwait<0>();
        __syncthreads();
        const uint32_t bb=smb+(kt&1)*TILE64;
        #pragma unroll
        for(int ks=0;ks<2;++ks){
            uint32_t ah[2][4], al[2][4], bh[4][2];
            #pragma unroll
            for(int mt=0;mt<2;++mt){
                uint32_t aa=bb+((wm*32+mt*16+lr)*LDA+ks*16+lc*8)*2;
                ldm4(ah[mt][0],ah[mt][1],ah[mt][2],ah[mt][3],aa);
                ldm4(al[mt][0],al[mt][1],al[mt][2],al[mt][3],aa+ARR_A);
            }
            #pragma unroll
            for(int nt=0;nt<4;++nt)
                ldm2(bh[nt][0],bh[nt][1],
                     bb+2*ARR_A+((wn*32+nt*8+l8)*LDA+ks*16+lk*8)*2);
            // sweep 1: hi*hi  (each acc touched once per sweep -> no chains)
            #pragma unroll
            for(int nt=0;nt<4;++nt)
                #pragma unroll
                for(int mt=0;mt<2;++mt)
                    mmabf(acc[mt][nt],ah[mt],bh[nt][0],bh[nt][1]);
            // sweep 2: lo*hi
            #pragma unroll
            for(int nt=0;nt<4;++nt)
                #pragma unroll
                for(int mt=0;mt<2;++mt)
                    mmabf(acc[mt][nt],al[mt],bh[nt][0],bh[nt][1]);
            // sweep 3: hi*lo (load bl here; each acc touched once)
            #pragma unroll
            for(int nt=0;nt<4;++nt){
                uint32_t bl0,bl1;
                ldm2(bl0,bl1,bb+2*ARR_A+ARR_Bw+((wn*32+nt*8+l8)*LDA+ks*16+lk*8)*2);
                #pragma unroll
                for(int mt=0;mt<2;++mt)
                    mmabf(acc[mt][nt],ah[mt],bl0,bl1);
            }
        }
        __syncthreads();
    }
    {
        int g=lane>>2, tg=lane&3;
        #pragma unroll
        for(int mt=0;mt<2;++mt){
            int r0=wm*32+mt*16+g;
            #pragma unroll
            for(int nt=0;nt<4;++nt){
                int col=wn*32+nt*8+2*tg;
                *(float2*)&Cs[r0*132+col]    =make_float2(acc[mt][nt][0],acc[mt][nt][1]);
                *(float2*)&Cs[(r0+8)*132+col]=make_float2(acc[mt][nt][2],acc[mt][nt][3]);
            }
        }
    }
    __syncthreads();
    epi(Cs);
}

__global__ __launch_bounds__(256,3) void qkv_hmma(const float* __restrict__ logc)
{
    extern __shared__ char smc[];
    const int z=blockIdx.z, m0=blockIdx.y*64, n0=blockIdx.x*128;
    const __nv_bfloat16* WH=g_wh+((size_t)z<<20);
    const __nv_bfloat16* WL=g_wl+((size_t)z<<20);
    const float c_=sp(*logc), sc=sqrtf(c_);
    const int tid=threadIdx.x;
    hmma_gemm_64x128(smc,g_xh,g_xl,WH,WL,m0,n0,[&](float* Cs){
        if(tid>=128) return;
        const int half=tid>>6, row=tid&63;
        const float* rp=&Cs[row*132+half*64];
        float ss=0.f;
        #pragma unroll
        for(int j=0;j<16;++j){
            float4 v=*(const float4*)&rp[j*4];
            ss=fmaf(v.x,v.x,fmaf(v.y,v.y,fmaf(v.z,v.z,fmaf(v.w,v.w,ss))));
        }
        const int m=m0+row, b=m>>10, s=m&1023;
        const int hh=blockIdx.x*2+half, bh=b*H_+hh;
        float n=fmaxf(sqrtf(ss),EPSF), scn=sc*n, t1=tanhf(scn);
        float scale;
        if(z<2) scale=t1/scn;
        else { float th=1.f-sc*EPSF; scale=(t1<th)?1.f:(atanhf(th)/scn); }
        if(z==2){
            #pragma unroll
            for(int j=0;j<64;++j){
                __nv_bfloat16 h,l; bfsplit(rp[j]*scale,h,l);
                g_vth[((size_t)bh*64+j)*1024+s]=h;
                g_vtl[((size_t)bh*64+j)*1024+s]=l;
            }
        }else{
            __nv_bfloat16* TH=(z==0)?g_qh16:g_kh16;
            __nv_bfloat16* TL=(z==0)?g_ql16:g_kl16;
            size_t base=((size_t)bh*1024+s)*64;
            #pragma unroll
            for(int j=0;j<16;++j){
                float4 v=*(const float4*)&rp[j*4];
                __nv_bfloat16 h0,l0,h1,l1,h2,l2,h3,l3;
                bfsplit(v.x*scale,h0,l0); bfsplit(v.y*scale,h1,l1);
                bfsplit(v.z*scale,h2,l2); bfsplit(v.w*scale,h3,l3);
                *(__nv_bfloat162*)&TH[base+j*4]  =__nv_bfloat162(h0,h1);
                *(__nv_bfloat162*)&TH[base+j*4+2]=__nv_bfloat162(h2,h3);
                *(__nv_bfloat162*)&TL[base+j*4]  =__nv_bfloat162(l0,l1);
                *(__nv_bfloat162*)&TL[base+j*4+2]=__nv_bfloat162(l2,l3);
            }
            ((z==0)?g_qns:g_kns)[bh*1024+s]=scale*scale*ss;
        }
    });
}

__global__ __launch_bounds__(256,3) void out_hmma(float* __restrict__ Cout)
{
    extern __shared__ char smc[];
    const int m0=blockIdx.y*64, n0=blockIdx.x*128;
    const int tid=threadIdx.x;
    hmma_gemm_64x128(smc,g_ath,g_atl,g_woh,g_wol,m0,n0,[&](float* Cs){
        if(tid>=128) return;
        const int half=tid>>6, row=tid&63;
        const float* rp=&Cs[row*132+half*64];
        float* dst=&Cout[(size_t)(m0+row)*1024+n0+half*64];
        #pragma unroll
        for(int j=0;j<16;++j) *(float4*)&dst[j*4]=*(const float4*)&rp[j*4];
    });
}

// ---------- Attention via HMMA: single-buffer KV, P unioned over S ----------
#define LQ 72
#define SST 72
#define QH_B 0
#define QL_B 18432
#define KV_B 36864           // KH 0, KL 9216, VH 18432, VL 27648
#define S_B  73728
#define PH_B 73728           // union with S
#define PL_B 92160
#define PC_B 110592
#define LR_B 111104
#define KN_B 111616
#define IOY_B 111872
#define ATSMB 112128

__global__ __launch_bounds__(256) void attn_hmma(const float* __restrict__ lp,
                                                 const float* __restrict__ bp)
{
    extern __shared__ char smc[];
    const uint32_t smb=smem_u32(smc);
    float* Sf =(float*)(smc+S_B);
    float* PCf=(float*)(smc+PC_B);
    float* LRf=(float*)(smc+LR_B);
    float* KNf=(float*)(smc+KN_B);
    float* IOYf=(float*)(smc+IOY_B);
    const int tid=threadIdx.x, lane=tid&31, wid=tid>>5;
    const int bh=blockIdx.y, q0=blockIdx.x*128;
    const float c_=sp(*lp), sc=sqrtf(c_), bis=sp(*bp)/sc, tc=2.f*c_;

    {
        const __nv_bfloat16* Qh=&g_qh16[((size_t)bh*1024+q0)*64];
        const __nv_bfloat16* Ql=&g_ql16[((size_t)bh*1024+q0)*64];
        #pragma unroll
        for(int it=0;it<8;++it){
            int idx=tid+it*256, r=idx>>4, q=idx&15;
            *(uint2*)(smc+QH_B+(r*LQ+q*4)*2)=*(const uint2*)&Qh[r*64+q*4];
            *(uint2*)(smc+QL_B+(r*LQ+q*4)*2)=*(const uint2*)&Ql[r*64+q*4];
        }
    }
    const __nv_bfloat16* Kh=&g_kh16[(size_t)bh*1024*64];
    const __nv_bfloat16* Kl=&g_kl16[(size_t)bh*1024*64];
    const __nv_bfloat16* Vh=&g_vth[(size_t)bh*64*1024];
    const __nv_bfloat16* Vl=&g_vtl[(size_t)bh*64*1024];

    auto stage_kv=[&](int k0){
        char* bb=smc+KV_B;
        #pragma unroll
        for(int it=0;it<8;++it){
            int idx=tid+it*256, arr=idx>>9, ch=idx&511, r=ch>>3, q=ch&7;
            uint32_t sa=smem_u32(bb+arr*9216+(r*LQ+q*8)*2);
            const __nv_bfloat16* gp=
                (arr==0)? Kh+(size_t)(k0+r)*64+q*8 :
                (arr==1)? Kl+(size_t)(k0+r)*64+q*8 :
                (arr==2)? Vh+(size_t)r*1024+k0+q*8 : Vl+(size_t)r*1024+k0+q*8;
            cpa16(sa,gp);
        }
        cpcommit();
    };
    stage_kv(0);

    const int srow=tid>>1, shalf=tid&1;
    float qn=g_qns[bh*1024+q0+srow];
    float iox=__fdividef(1.f,1.f-c_*qn);
    float knreg=(tid<64)? g_kns[bh*1024+tid] : 0.f;
    float mold=-INFINITY, lhalf=0.f;
    float oacc[8][4]={};
    const int lr=lane&15, lc=lane>>4, l8=lane&7, lk=(lane>>3)&1;
    const int g=lane>>2, tg=lane&3;

    for(int kt=0;kt<16;++kt){
        if(tid<64){
            KNf[tid]=knreg;
            IOYf[tid]=__fdividef(1.f,1.f-c_*knreg);
            if(kt<15) knreg=g_kns[bh*1024+(kt+1)*64+tid];
        }
        cpwait<0>();
        __syncthreads();
        const uint32_t kvb=smb+KV_B;
        // S = Q K^T  (sweep-ordered split MMAs)
        {
            float sacc[8][4]={};
            #pragma unroll
            for(int ks=0;ks<4;++ks){
                uint32_t ah[4],al[4],kh[8][2];
                uint32_t aa=smb+QH_B+((16*wid+lr)*LQ+ks*16+lc*8)*2;
                ldm4(ah[0],ah[1],ah[2],ah[3],aa);
                ldm4(al[0],al[1],al[2],al[3],aa+(QL_B-QH_B));
                #pragma unroll
                for(int nt=0;nt<8;++nt)
                    ldm2(kh[nt][0],kh[nt][1],kvb+((nt*8+l8)*LQ+ks*16+lk*8)*2);
                #pragma unroll
                for(int nt=0;nt<8;++nt) mmabf(sacc[nt],ah,kh[nt][0],kh[nt][1]);
                #pragma unroll
                for(int nt=0;nt<8;++nt) mmabf(sacc[nt],al,kh[nt][0],kh[nt][1]);
                #pragma unroll
                for(int nt=0;nt<8;++nt){
                    uint32_t kl0,kl1;
                    ldm2(kl0,kl1,kvb+9216+((nt*8+l8)*LQ+ks*16+lk*8)*2);
                    mmabf(sacc[nt],ah,kl0,kl1);
                }
            }
            #pragma unroll
            for(int nt=0;nt<8;++nt){
                *(float2*)&Sf[(16*wid+g)*SST+nt*8+2*tg]  =make_float2(sacc[nt][0],sacc[nt][1]);
                *(float2*)&Sf[(16*wid+8+g)*SST+nt*8+2*tg]=make_float2(sacc[nt][2],sacc[nt][3]);
            }
        }
        __syncthreads();
        // score (reads S) ... sync ... softmax + P write (P unioned over S)
        {
            float sv[32];
            const float* sp_=&Sf[srow*SST+shalf*32];
            #pragma unroll
            for(int j=0;j<8;++j){
                float4 s4=*(const float4*)&sp_[j*4];
                float v[4]={s4.x,s4.y,s4.z,s4.w};
                #pragma unroll
                for(int u=0;u<4;++u){
                    int t=shalf*32+j*4+u;
                    float dsq=fmaf(-2.f,v[u],qn+KNf[t]);
                    float tt=fminf(iox*IOYf[t],1.0e5f);
                    float a0=fmaxf(fmaf(tc*dsq,tt,1.f),1.f+EPSF);
                    sv[j*4+u]=-bis*lg2ap(a0+sqap(fmaf(a0,a0,-1.f)));
                }
            }
            __syncthreads();
            float tm=-INFINITY;
            #pragma unroll
            for(int j=0;j<32;++j) tm=fmaxf(tm,sv[j]);
            tm=fmaxf(tm,__shfl_xor_sync(~0u,tm,1));
            float mn=fmaxf(mold,tm);
            float pc=ex2ap(mold-mn);
            mold=mn;
            float ls=0.f;
            #pragma unroll
            for(int j=0;j<32;++j){ float p=ex2ap(sv[j]-mn); sv[j]=p; ls+=p; }
            lhalf=lhalf*pc+ls;
            if(shalf==0) PCf[srow]=pc;
            #pragma unroll
            for(int j=0;j<16;++j){
                __nv_bfloat16 h0,l0,h1,l1;
                bfsplit(sv[2*j],h0,l0); bfsplit(sv[2*j+1],h1,l1);
                int col=shalf*32+2*j;
                *(__nv_bfloat162*)(smc+PH_B+(srow*LQ+col)*2)=__nv_bfloat162(h0,h1);
                *(__nv_bfloat162*)(smc+PL_B+(srow*LQ+col)*2)=__nv_bfloat162(l0,l1);
            }
        }
        __syncthreads();
        // O = O*pc + P V  (sweep-ordered split MMAs)
        {
            float pc0=PCf[16*wid+g], pc8=PCf[16*wid+8+g];
            #pragma unroll
            for(int nt=0;nt<8;++nt){
                oacc[nt][0]*=pc0; oacc[nt][1]*=pc0;
                oacc[nt][2]*=pc8; oacc[nt][3]*=pc8;
            }
            #pragma unroll
            for(int ks=0;ks<4;++ks){
                uint32_t ph[4],pl[4],vh[8][2];
                uint32_t pa=smb+PH_B+((16*wid+lr)*LQ+ks*16+lc*8)*2;
                ldm4(ph[0],ph[1],ph[2],ph[3],pa);
                ldm4(pl[0],pl[1],pl[2],pl[3],pa+(PL_B-PH_B));
                #pragma unroll
                for(int nt=0;nt<8;++nt)
                    ldm2(vh[nt][0],vh[nt][1],kvb+18432+((nt*8+l8)*LQ+ks*16+lk*8)*2);
                #pragma unroll
                for(int nt=0;nt<8;++nt) mmabf(oacc[nt],ph,vh[nt][0],vh[nt][1]);
                #pragma unroll
                for(int nt=0;nt<8;++nt) mmabf(oacc[nt],pl,vh[nt][0],vh[nt][1]);
                #pragma unroll
                for(int nt=0;nt<8;++nt){
                    uint32_t vl0,vl1;
                    ldm2(vl0,vl1,kvb+27648+((nt*8+l8)*LQ+ks*16+lk*8)*2);
                    mmabf(oacc[nt],ph,vl0,vl1);
                }
            }
        }
        __syncthreads();
        if(kt<15) stage_kv((kt+1)*64);
    }
    {
        float lf=lhalf+__shfl_xor_sync(~0u,lhalf,1);
        if(shalf==0) LRf[srow]=__fdividef(1.f,lf);
    }
    __syncthreads();
    {
        float i0=LRf[16*wid+g], i8=LRf[16*wid+8+g];
        float ss0=0.f, ss8=0.f;
        #pragma unroll
        for(int nt=0;nt<8;++nt){
            float e0=oacc[nt][0]*i0, e1=oacc[nt][1]*i0;
            float e2=oacc[nt][2]*i8, e3=oacc[nt][3]*i8;
            ss0=fmaf(e0,e0,fmaf(e1,e1,ss0));
            ss8=fmaf(e2,e2,fmaf(e3,e3,ss8));
        }
        ss0+=__shfl_xor_sync(~0u,ss0,1); ss0+=__shfl_xor_sync(~0u,ss0,2);
        ss8+=__shfl_xor_sync(~0u,ss8,1); ss8+=__shfl_xor_sync(~0u,ss8,2);
        const float th=1.f-sc*EPSF;
        float n0=fmaxf(sqrtf(ss0),EPSF), scn0=sc*n0, t10=tanhf(scn0);
        float sc0=(t10<th)?i0:(atanhf(th)/scn0)*i0;
        float n8=fmaxf(sqrtf(ss8),EPSF), scn8=sc*n8, t18=tanhf(scn8);
        float sc8=(t18<th)?i8:(atanhf(th)/scn8)*i8;
        const int b=bh>>4, hh=bh&15;
        const int s0g=q0+16*wid+g, s8g=s0g+8;
        #pragma unroll
        for(int nt=0;nt<8;++nt){
            int col=hh*64+nt*8+2*tg;
            __nv_bfloat16 h0,l0,h1,l1;
            bfsplit(oacc[nt][0]*sc0,h0,l0); bfsplit(oacc[nt][1]*sc0,h1,l1);
            *(__nv_bfloat162*)&g_ath[((size_t)(b*1024+s0g))*1024+col]=__nv_bfloat162(h0,h1);
            *(__nv_bfloat162*)&g_atl[((size_t)(b*1024+s0g))*1024+col]=__nv_bfloat162(l0,l1);
            bfsplit(oacc[nt][2]*sc8,h0,l0); bfsplit(oacc[nt][3]*sc8,h1,l1);
            *(__nv_bfloat162*)&g_ath[((size_t)(b*1024+s8g))*1024+col]=__nv_bfloat162(h0,h1);
            *(__nv_bfloat162*)&g_atl[((size_t)(b*1024+s8g))*1024+col]=__nv_bfloat162(l0,l1);
        }
    }
}

extern "C" void kernel_launch(void* const* d_in, const int* in_sizes, int n_in,
                              void* d_out, int out_size)
{
    (void)in_sizes;(void)n_in;(void)out_size;
    const float* x   =(const float*)d_in[0];
    const float* Wq  =(const float*)d_in[1];
    const float* Wk  =(const float*)d_in[2];
    const float* Wv  =(const float*)d_in[3];
    const float* Wo  =(const float*)d_in[4];
    const float* logc=(const float*)d_in[5];
    const float* beta=(const float*)d_in[6];
    float* out=(float*)d_out;

    cudaFuncSetAttribute(qkv_hmma, cudaFuncAttributeMaxDynamicSharedMemorySize, QSMB);
    cudaFuncSetAttribute(attn_hmma, cudaFuncAttributeMaxDynamicSharedMemorySize, ATSMB);
    cudaFuncSetAttribute(out_hmma, cudaFuncAttributeMaxDynamicSharedMemorySize, QSMB);

    split_k<<<2048,256>>>(x,Wq,Wk,Wv,Wo);
    qkv_hmma<<<dim3(8,32,3),256,QSMB>>>(logc);
    attn_hmma<<<dim3(8,32),256,ATSMB>>>(logc,beta);
    out_hmma<<<dim3(8,32),256,QSMB>>>(out);
}